// round 15
// baseline (speedup 1.0000x reference)
#include <cuda_runtime.h>
#include <cuda_fp16.h>
#include <mma.h>
#include <cstdint>
using namespace nvcuda;

#define BB 8
#define NN 3136
#define CC 512
#define C4 128
#define NHEADS 8
#define P2 784
#define MKV 196
#define MTOK (BB*NN)

// ---------------- scratch ----------------
__device__ __half g_xh  [MTOK*CC];
__device__ __half g_qh  [MTOK*CC];
__device__ float  g_rtmp[MTOK*C4];
__device__ __half g_dwt [BB*P2*CC];       // NHWC
__device__ __half g_c3  [BB*P2*CC];       // NHWC
__device__ float  g_kvin[BB*MKV*CC];
__device__ __half g_kvinh[BB*MKV*CC];
__device__ __half g_kvh [BB*MKV*2*CC];
__device__ __half g_cath[MTOK*(CC+C4)];
__device__ __half g_qwh  [CC*CC];
__device__ __half g_rwh  [C4*CC];
__device__ __half g_fwh  [CC*CC*9];       // [oc][kyx][ic]
__device__ __half g_kvewh[CC*CC*4];       // [oc][kyx][ic]
__device__ __half g_kvwh [2*CC*CC];
__device__ __half g_pwh  [CC*(CC+C4)];

// ---------------- cp.async helpers ----------------
__device__ __forceinline__ unsigned int s2u(const void* p) {
    return (unsigned int)__cvta_generic_to_shared(p);
}
__device__ __forceinline__ void cp16(unsigned int d, const void* s) {
    asm volatile("cp.async.cg.shared.global [%0], [%1], 16;" :: "r"(d), "l"(s) : "memory");
}
__device__ __forceinline__ void cp16p(unsigned int d, const void* s, bool pred) {
    int sz = pred ? 16 : 0;
    asm volatile("cp.async.cg.shared.global [%0], [%1], 16, %2;" :: "r"(d), "l"(s), "r"(sz) : "memory");
}
__device__ __forceinline__ void cpcommit() { asm volatile("cp.async.commit_group;" ::: "memory"); }
__device__ __forceinline__ void cpwait0() { asm volatile("cp.async.wait_group 0;" ::: "memory"); }
__device__ __forceinline__ void cpwait1() { asm volatile("cp.async.wait_group 1;" ::: "memory"); }

// ---------------- conversion kernels ----------------
__global__ void f2h8(const float* __restrict__ s, __half* __restrict__ d, int n) {
    int i = (blockIdx.x * blockDim.x + threadIdx.x) * 8;
    if (i >= n) return;
    float4 a = *(const float4*)&s[i];
    float4 b = *(const float4*)&s[i + 4];
    __half2 h0 = __floats2half2_rn(a.x, a.y);
    __half2 h1 = __floats2half2_rn(a.z, a.w);
    __half2 h2 = __floats2half2_rn(b.x, b.y);
    __half2 h3 = __floats2half2_rn(b.z, b.w);
    uint4 o;
    o.x = *(unsigned int*)&h0;
    o.y = *(unsigned int*)&h1;
    o.z = *(unsigned int*)&h2;
    o.w = *(unsigned int*)&h3;
    *(uint4*)&d[i] = o;
}
__global__ void reorder_w3(const float* __restrict__ w, __half* __restrict__ o) {
    int idx = blockIdx.x * 256 + threadIdx.x;
    if (idx >= 512 * 4608) return;
    int oc = idx / 4608;
    int r = idx - oc * 4608;
    int kyx = r >> 9;
    int ic = r & 511;
    o[idx] = __float2half(w[((long)(oc * 512 + ic)) * 9 + kyx]);
}
__global__ void reorder_w2(const float* __restrict__ w, __half* __restrict__ o) {
    int idx = blockIdx.x * 256 + threadIdx.x;
    if (idx >= 512 * 2048) return;
    int oc = idx >> 11;
    int r = idx & 2047;
    int kyx = r >> 9;
    int ic = r & 511;
    o[idx] = __float2half(w[((long)(oc * 512 + ic)) * 4 + kyx]);
}

__device__ __forceinline__ void st_out(float* p, float v) { *p = v; }
__device__ __forceinline__ void st_out(__half* p, float v) { *p = __float2half(v); }

// =====================================================================
// gemm core 128x128, BK=64, 2-stage cp.async, 8 warps 64x32
// =====================================================================
#define GEMM_SMEM (2*128*72*2*2)
#define LDK 72
typedef wmma::fragment<wmma::accumulator, 16, 16, 16, float> AccFrag;

template<typename LT>
__device__ __forceinline__ void gemm_core(char* smem, int KT, LT loadTile,
                                          AccFrag (&acc)[4][2], int wr, int wc) {
    __half* As = (__half*)smem;
    __half* Bs = (__half*)(smem + 36864);
    #pragma unroll
    for (int i = 0; i < 4; i++)
        #pragma unroll
        for (int j = 0; j < 2; j++) wmma::fill_fragment(acc[i][j], 0.f);
    loadTile(0, 0); cpcommit();
    for (int kt = 0; kt < KT; kt++) {
        int cur = kt & 1;
        if (kt + 1 < KT) { loadTile(kt + 1, cur ^ 1); cpcommit(); cpwait1(); }
        else cpwait0();
        __syncthreads();
        #pragma unroll
        for (int kk = 0; kk < 64; kk += 16) {
            wmma::fragment<wmma::matrix_a, 16, 16, 16, __half, wmma::row_major> af[4];
            wmma::fragment<wmma::matrix_b, 16, 16, 16, __half, wmma::col_major> bf[2];
            #pragma unroll
            for (int i = 0; i < 4; i++)
                wmma::load_matrix_sync(af[i], &As[(cur * 128 + wr * 64 + i * 16) * LDK + kk], LDK);
            #pragma unroll
            for (int j = 0; j < 2; j++)
                wmma::load_matrix_sync(bf[j], &Bs[(cur * 128 + wc * 32 + j * 16) * LDK + kk], LDK);
            #pragma unroll
            for (int i = 0; i < 4; i++)
                #pragma unroll
                for (int j = 0; j < 2; j++)
                    wmma::mma_sync(acc[i][j], af[i], bf[j], acc[i][j]);
        }
        __syncthreads();
    }
}

// =====================================================================
// gemm core 64x128, BK=64, 2-stage, 8 warps 32x32 (wave-starved shapes)
// smem: As 2x64x72h @0 | Bs 2x128x72h @18432
// =====================================================================
#define GEMM64_SMEM (2*64*72*2 + 2*128*72*2)

template<typename LT>
__device__ __forceinline__ void gemm_core64(char* smem, int KT, LT loadTile,
                                            AccFrag (&acc)[2][2], int wm, int wn) {
    __half* As = (__half*)smem;
    __half* Bs = (__half*)(smem + 18432);
    #pragma unroll
    for (int i = 0; i < 2; i++)
        #pragma unroll
        for (int j = 0; j < 2; j++) wmma::fill_fragment(acc[i][j], 0.f);
    loadTile(0, 0); cpcommit();
    for (int kt = 0; kt < KT; kt++) {
        int cur = kt & 1;
        if (kt + 1 < KT) { loadTile(kt + 1, cur ^ 1); cpcommit(); cpwait1(); }
        else cpwait0();
        __syncthreads();
        #pragma unroll
        for (int kk = 0; kk < 64; kk += 16) {
            wmma::fragment<wmma::matrix_a, 16, 16, 16, __half, wmma::row_major> af[2];
            wmma::fragment<wmma::matrix_b, 16, 16, 16, __half, wmma::col_major> bf[2];
            #pragma unroll
            for (int i = 0; i < 2; i++)
                wmma::load_matrix_sync(af[i], &As[(cur * 64 + wm * 32 + i * 16) * LDK + kk], LDK);
            #pragma unroll
            for (int j = 0; j < 2; j++)
                wmma::load_matrix_sync(bf[j], &Bs[(cur * 128 + wn * 32 + j * 16) * LDK + kk], LDK);
            #pragma unroll
            for (int i = 0; i < 2; i++)
                #pragma unroll
                for (int j = 0; j < 2; j++)
                    wmma::mma_sync(acc[i][j], af[i], bf[j], acc[i][j]);
        }
        __syncthreads();
    }
}

// =====================================================================
// gemm16: 128x128 core; C[m,n] = sum_k A[m,k] B[n,k] + bias[n]
// =====================================================================
template<typename OT>
__global__ __launch_bounds__(256)
void gemm16(const __half* __restrict__ A, const __half* __restrict__ B,
            const float* __restrict__ bias, OT* __restrict__ C,
            int M, int N, int K, int ldc) {
    extern __shared__ char smem[];
    __half* As = (__half*)smem;
    __half* Bs = (__half*)(smem + 36864);
    float*  Es = (float*)smem;
    int tid = threadIdx.x;
    int warp = tid >> 5;
    int lane = tid & 31;
    int wr = warp & 1;
    int wc = warp >> 1;
    int m0 = blockIdx.y * 128;
    int n0 = blockIdx.x * 128;
    AccFrag acc[4][2];
    auto loadTile = [&](int kt, int buf) {
        int k0 = kt << 6;
        #pragma unroll
        for (int i = 0; i < 4; i++) {
            int c = tid + i * 256;
            int row = c >> 3;
            int off = (c & 7) * 8;
            int m = m0 + row;
            bool ok = (m < M);
            cp16p(s2u(&As[(buf * 128 + row) * LDK + off]), &A[(long)(ok ? m : 0) * K + k0 + off], ok);
            cp16(s2u(&Bs[(buf * 128 + row) * LDK + off]), &B[(long)(n0 + row) * K + k0 + off]);
        }
    };
    gemm_core(smem, K >> 6, loadTile, acc, wr, wc);
    __syncthreads();
    #pragma unroll
    for (int i = 0; i < 4; i++)
        #pragma unroll
        for (int j = 0; j < 2; j++) {
            wmma::store_matrix_sync(&Es[warp * 384], acc[i][j], 24, wmma::mem_row_major);
            __syncwarp();
            #pragma unroll
            for (int e = 0; e < 8; e++) {
                int idx = lane + e * 32;
                int r = idx >> 4;
                int c = idx & 15;
                int m = m0 + wr * 64 + i * 16 + r;
                int n = n0 + wc * 32 + j * 16 + c;
                if (m < M) st_out(&C[(long)m * ldc + n], Es[warp * 384 + r * 24 + c] + bias[n]);
            }
            __syncwarp();
        }
}

// =====================================================================
// gemm16_64: 64x128 core; for reduce (N=128) and kv (small M)
// =====================================================================
template<typename OT>
__global__ __launch_bounds__(256)
void gemm16_64(const __half* __restrict__ A, const __half* __restrict__ B,
               const float* __restrict__ bias, OT* __restrict__ C,
               int M, int N, int K, int ldc) {
    extern __shared__ char smem[];
    __half* As = (__half*)smem;
    __half* Bs = (__half*)(smem + 18432);
    float*  Es = (float*)smem;
    int tid = threadIdx.x;
    int warp = tid >> 5;
    int lane = tid & 31;
    int wm = warp >> 2;
    int wn = warp & 3;
    int m0 = blockIdx.y * 64;
    int n0 = blockIdx.x * 128;
    AccFrag acc[2][2];
    auto loadTile = [&](int kt, int buf) {
        int k0 = kt << 6;
        #pragma unroll
        for (int i = 0; i < 2; i++) {
            int c = tid + i * 256;
            int row = c >> 3;
            int off = (c & 7) * 8;
            int m = m0 + row;
            bool ok = (m < M);
            cp16p(s2u(&As[(buf * 64 + row) * LDK + off]), &A[(long)(ok ? m : 0) * K + k0 + off], ok);
        }
        #pragma unroll
        for (int i = 0; i < 4; i++) {
            int c = tid + i * 256;
            int row = c >> 3;
            int off = (c & 7) * 8;
            cp16(s2u(&Bs[(buf * 128 + row) * LDK + off]), &B[(long)(n0 + row) * K + k0 + off]);
        }
    };
    gemm_core64(smem, K >> 6, loadTile, acc, wm, wn);
    __syncthreads();
    #pragma unroll
    for (int i = 0; i < 2; i++)
        #pragma unroll
        for (int j = 0; j < 2; j++) {
            wmma::store_matrix_sync(&Es[warp * 384], acc[i][j], 24, wmma::mem_row_major);
            __syncwarp();
            #pragma unroll
            for (int e = 0; e < 8; e++) {
                int idx = lane + e * 32;
                int r = idx >> 4;
                int c = idx & 15;
                int m = m0 + wm * 32 + i * 16 + r;
                int n = n0 + wn * 32 + j * 16 + c;
                if (m < M) st_out(&C[(long)m * ldc + n], Es[warp * 384 + r * 24 + c] + bias[n]);
            }
            __syncwarp();
        }
}

// =====================================================================
// conv3x3 implicit GEMM (NHWC), 64x128 tiles; M=6272,N=512,K=4608
// =====================================================================
__global__ __launch_bounds__(256)
void conv3_g(const __half* __restrict__ dwt, const __half* __restrict__ w,
             const float* __restrict__ cb, const float* __restrict__ cg,
             const float* __restrict__ cbeta, __half* __restrict__ out) {
    extern __shared__ char smem[];
    float* Es = (float*)smem;
    int tid = threadIdx.x;
    int warp = tid >> 5;
    int lane = tid & 31;
    int wm = warp >> 2;
    int wn = warp & 3;
    int m0 = blockIdx.y * 64;
    int n0 = blockIdx.x * 128;
    __half* As = (__half*)smem;
    __half* Bs = (__half*)(smem + 18432);
    int pre_b[2], pre_y[2], pre_x[2];
    #pragma unroll
    for (int i = 0; i < 2; i++) {
        int c = tid + i * 256;
        int row = c >> 3;
        int m = m0 + row;
        int b = m / P2;
        int p = m - b * P2;
        pre_b[i] = b;
        pre_y[i] = p / 28;
        pre_x[i] = p - (p / 28) * 28;
    }
    AccFrag acc[2][2];
    auto loadTile = [&](int kt, int buf) {
        int k0 = kt << 6;
        #pragma unroll
        for (int i = 0; i < 2; i++) {
            int c = tid + i * 256;
            int row = c >> 3;
            int off = (c & 7) * 8;
            int k = k0 + off;
            int kyx = k >> 9;
            int ic = k & 511;
            int ky = kyx / 3;
            int kx = kyx - ky * 3;
            int iy = pre_y[i] + ky - 1;
            int ix = pre_x[i] + kx - 1;
            bool ok = (iy >= 0 && iy < 28 && ix >= 0 && ix < 28);
            int iyc = ok ? iy : 0;
            int ixc = ok ? ix : 0;
            cp16p(s2u(&As[(buf * 64 + row) * LDK + off]),
                  &dwt[((long)(pre_b[i] * P2 + iyc * 28 + ixc) << 9) + ic], ok);
        }
        #pragma unroll
        for (int i = 0; i < 4; i++) {
            int c = tid + i * 256;
            int row = c >> 3;
            int off = (c & 7) * 8;
            cp16(s2u(&Bs[(buf * 128 + row) * LDK + off]), &w[(long)(n0 + row) * 4608 + k0 + off]);
        }
    };
    gemm_core64(smem, 72, loadTile, acc, wm, wn);
    __syncthreads();
    const float invs = rsqrtf(1.f + 1e-5f);
    #pragma unroll
    for (int i = 0; i < 2; i++)
        #pragma unroll
        for (int j = 0; j < 2; j++) {
            wmma::store_matrix_sync(&Es[warp * 384], acc[i][j], 24, wmma::mem_row_major);
            __syncwarp();
            #pragma unroll
            for (int e = 0; e < 8; e++) {
                int idx = lane + e * 32;
                int r = idx >> 4;
                int c = idx & 15;
                int m = m0 + wm * 32 + i * 16 + r;
                int n = n0 + wn * 32 + j * 16 + c;
                float v = Es[warp * 384 + r * 24 + c] + cb[n];
                v = v * (cg[n] * invs) + cbeta[n];
                out[((long)m << 9) + n] = __float2half(fmaxf(v, 0.f));
            }
            __syncwarp();
        }
}

// =====================================================================
// kve 2x2 s2 conv implicit GEMM, 64x128 tiles; M=1568,N=512,K=2048
// =====================================================================
__global__ __launch_bounds__(256)
void kve_g(const __half* __restrict__ c3, const __half* __restrict__ w,
           const float* __restrict__ bias, float* __restrict__ out) {
    extern __shared__ char smem[];
    float* Es = (float*)smem;
    int tid = threadIdx.x;
    int warp = tid >> 5;
    int lane = tid & 31;
    int wm = warp >> 2;
    int wn = warp & 3;
    int m0 = blockIdx.y * 64;
    int n0 = blockIdx.x * 128;
    __half* As = (__half*)smem;
    __half* Bs = (__half*)(smem + 18432);
    int pre_s[2];
    bool pre_v[2];
    #pragma unroll
    for (int i = 0; i < 2; i++) {
        int c = tid + i * 256;
        int row = c >> 3;
        int m = m0 + row;
        pre_v[i] = (m < BB * MKV);
        int mm = pre_v[i] ? m : 0;
        int b = mm / MKV;
        int p = mm - b * MKV;
        int oy = p / 14;
        int ox = p - (p / 14) * 14;
        pre_s[i] = b * P2 + 2 * oy * 28 + 2 * ox;
    }
    AccFrag acc[2][2];
    auto loadTile = [&](int kt, int buf) {
        int k0 = kt << 6;
        #pragma unroll
        for (int i = 0; i < 2; i++) {
            int c = tid + i * 256;
            int row = c >> 3;
            int off = (c & 7) * 8;
            int k = k0 + off;
            int kyx = k >> 9;
            int ic = k & 511;
            int ky = kyx >> 1;
            int kx = kyx & 1;
            cp16p(s2u(&As[(buf * 64 + row) * LDK + off]),
                  &c3[((long)(pre_s[i] + ky * 28 + kx) << 9) + ic], pre_v[i]);
        }
        #pragma unroll
        for (int i = 0; i < 4; i++) {
            int c = tid + i * 256;
            int row = c >> 3;
            int off = (c & 7) * 8;
            cp16(s2u(&Bs[(buf * 128 + row) * LDK + off]), &w[(long)(n0 + row) * 2048 + k0 + off]);
        }
    };
    gemm_core64(smem, 32, loadTile, acc, wm, wn);
    __syncthreads();
    #pragma unroll
    for (int i = 0; i < 2; i++)
        #pragma unroll
        for (int j = 0; j < 2; j++) {
            wmma::store_matrix_sync(&Es[warp * 384], acc[i][j], 24, wmma::mem_row_major);
            __syncwarp();
            #pragma unroll
            for (int e = 0; e < 8; e++) {
                int idx = lane + e * 32;
                int r = idx >> 4;
                int c = idx & 15;
                int m = m0 + wm * 32 + i * 16 + r;
                int n = n0 + wn * 32 + j * 16 + c;
                if (m < BB * MKV) out[(long)m * CC + n] = Es[warp * 384 + r * 24 + c] + bias[n];
            }
            __syncwarp();
        }
}

// ---------------- BN+ReLU+fp16+DWT ----------------
__global__ void dwt_k(const float* __restrict__ rtmp, const float* __restrict__ g,
                      const float* __restrict__ beta, __half* __restrict__ dwt) {
    int idx = blockIdx.x * blockDim.x + threadIdx.x;
    if (idx >= BB * C4 * P2) return;
    int c = idx & 127;
    int p = (idx >> 7) % P2;
    int b = idx / (C4 * P2);
    int y2 = p / 28;
    int x2 = p % 28;
    float s = g[c] * rsqrtf(1.f + 1e-5f);
    float bt = beta[c];
    const __half hhalf = __float2half(0.5f);
    __half xh[2][2];
    #pragma unroll
    for (int dy = 0; dy < 2; dy++)
        #pragma unroll
        for (int dx = 0; dx < 2; dx++) {
            int n = (2 * y2 + dy) * 56 + (2 * x2 + dx);
            float v = rtmp[((long)(b * NN + n)) * C4 + c];
            v = fmaxf(v * s + bt, 0.f);
            xh[dy][dx] = __hmul(__float2half(v), hhalf);
        }
    __half x1 = xh[0][0], x2h = xh[1][0], x3 = xh[0][1], x4 = xh[1][1];
    __half ll = __hadd(__hadd(__hadd(x1, x2h), x3), x4);
    __half hl = __hadd(__hadd(__hsub(__hneg(x1), x2h), x3), x4);
    __half lh = __hadd(__hsub(__hadd(__hneg(x1), x2h), x3), x4);
    __half hh = __hadd(__hsub(__hsub(x1, x2h), x3), x4);
    long base = ((long)(b * P2 + p) << 9) + c;
    dwt[base]       = ll;
    dwt[base + 128] = hl;
    dwt[base + 256] = lh;
    dwt[base + 384] = hh;
}

// ---------------- IDWT -> cath[:, 512:] ----------------
__global__ void idwt_k(const __half* __restrict__ c3, __half* __restrict__ cat) {
    int idx = blockIdx.x * blockDim.x + threadIdx.x;
    if (idx >= BB * C4 * P2) return;
    int c = idx & 127;
    int p = (idx >> 7) % P2;
    int b = idx / (C4 * P2);
    int y2 = p / 28;
    int x2 = p % 28;
    long base = ((long)(b * P2 + p) << 9) + c;
    __half ll = c3[base], hl = c3[base + 128], lh = c3[base + 256], hh = c3[base + 384];
    const __half hhalf = __float2half(0.5f);
    __half p1 = __hmul(__hadd(__hsub(__hsub(ll, hl), lh), hh), hhalf);
    __half p2 = __hmul(__hsub(__hadd(__hsub(ll, hl), lh), hh), hhalf);
    __half p3 = __hmul(__hsub(__hsub(__hadd(ll, hl), lh), hh), hhalf);
    __half p4 = __hmul(__hadd(__hadd(__hadd(ll, hl), lh), hh), hhalf);
    int n00 = (2 * y2) * 56 + 2 * x2;
    long cb = ((long)(b * NN)) * 640 + 512 + c;
    cat[cb + (long)n00 * 640]        = p1;
    cat[cb + (long)(n00 + 1) * 640]  = p3;
    cat[cb + (long)(n00 + 56) * 640] = p2;
    cat[cb + (long)(n00 + 57) * 640] = p4;
}

// ---------------- LayerNorm ----------------
__global__ void layernorm_k(const float* __restrict__ buf, const float* __restrict__ g,
                            const float* __restrict__ bta, __half* __restrict__ outh) {
    int row = blockIdx.x;
    const float* p = buf + (long)row * CC;
    __shared__ float red[16];
    int tid = threadIdx.x;
    float v = p[tid];
    float s = v;
    #pragma unroll
    for (int o = 16; o > 0; o >>= 1) s += __shfl_xor_sync(~0u, s, o);
    if ((tid & 31) == 0) red[tid >> 5] = s;
    __syncthreads();
    if (tid < 16) {
        float t = red[tid];
        #pragma unroll
        for (int o = 8; o > 0; o >>= 1) t += __shfl_xor_sync(0xffffu, t, o);
        if (tid == 0) red[0] = t;
    }
    __syncthreads();
    float mu = red[0] * (1.f / 512.f);
    __syncthreads();
    float d = v - mu;
    float s2 = d * d;
    #pragma unroll
    for (int o = 16; o > 0; o >>= 1) s2 += __shfl_xor_sync(~0u, s2, o);
    if ((tid & 31) == 0) red[tid >> 5] = s2;
    __syncthreads();
    if (tid < 16) {
        float t = red[tid];
        #pragma unroll
        for (int o = 8; o > 0; o >>= 1) t += __shfl_xor_sync(0xffffu, t, o);
        if (tid == 0) red[0] = t;
    }
    __syncthreads();
    float var = red[0] * (1.f / 512.f);
    outh[(long)row * CC + tid] = __float2half(d * (1.f / sqrtf(var + 1e-5f)) * g[tid] + bta[tid]);
}

// =====================================================================
// WMMA attention, 256 q rows per block (4 x 64-row subtiles share K/V)
// smem: qs 256x80h | ks 224x80h | vs 224x80h | Ps 64x240h | Ss 64x232f
// =====================================================================
#define ATTN_SMEM (256*80*2 + 224*80*2*2 + 64*240*2 + 64*232*4)
__global__ __launch_bounds__(256)
void attn_w(const __half* __restrict__ qh, const __half* __restrict__ kvh,
            __half* __restrict__ cat) {
    extern __shared__ char smem[];
    __half* qs  = (__half*)smem;                             // 256 x 80
    __half* ks  = (__half*)(smem + 40960);                   // 224 x 80
    __half* vs  = (__half*)(smem + 40960 + 35840);           // 224 x 80
    __half* Ps  = (__half*)(smem + 40960 + 71680);           // 64 x 240
    float*  Ss  = (float*)(smem + 40960 + 71680 + 30720);    // 64 x 232
    int b = blockIdx.x >> 3;
    int h = blockIdx.x & 7;
    int n0 = blockIdx.y * 256;
    int rem = NN - n0;
    int nsub = (rem >= 256) ? 4 : ((rem + 63) >> 6);
    int tid = threadIdx.x;
    int warp = tid >> 5;
    int lane = tid & 31;

    #pragma unroll
    for (int i = 0; i < 8; i++) {
        int c = tid + i * 256;
        int row = c >> 3;
        int off = (c & 7) * 8;
        bool ok = (n0 + row < NN);
        int rowc = ok ? row : 0;
        cp16p(s2u(&qs[row * 80 + off]), &qh[((long)(b * NN + n0 + rowc) << 9) + h * 64 + off], ok);
    }
    #pragma unroll
    for (int i = 0; i < 7; i++) {
        int c = tid + i * 256;
        int row = c >> 3;
        int off = (c & 7) * 8;
        bool ok = row < MKV;
        int rc = ok ? row : 0;
        const __half* base = &kvh[((long)(b * MKV + rc) << 10) + h * 64 + off];
        cp16p(s2u(&ks[row * 80 + off]), base, ok);
        cp16p(s2u(&vs[row * 80 + off]), base + 512, ok);
    }
    cpcommit(); cpwait0();
    __syncthreads();

    for (int qt = 0; qt < nsub; qt++) {
        __half* qsub = qs + qt * 64 * 80;
        {
            int mr = warp >> 1;
            int nh = warp & 1;
            wmma::fragment<wmma::accumulator, 16, 16, 16, float> sacc[7];
            #pragma unroll
            for (int j = 0; j < 7; j++) wmma::fill_fragment(sacc[j], 0.f);
            #pragma unroll
            for (int kk = 0; kk < 64; kk += 16) {
                wmma::fragment<wmma::matrix_a, 16, 16, 16, __half, wmma::row_major> af;
                wmma::load_matrix_sync(af, &qsub[(mr * 16) * 80 + kk], 80);
                #pragma unroll
                for (int j = 0; j < 7; j++) {
                    wmma::fragment<wmma::matrix_b, 16, 16, 16, __half, wmma::col_major> bf;
                    wmma::load_matrix_sync(bf, &ks[((nh * 7 + j) * 16) * 80 + kk], 80);
                    wmma::mma_sync(sacc[j], af, bf, sacc[j]);
                }
            }
            #pragma unroll
            for (int j = 0; j < 7; j++)
                wmma::store_matrix_sync(&Ss[(mr * 16) * 232 + (nh * 7 + j) * 16], sacc[j], 232,
                                        wmma::mem_row_major);
        }
        __syncthreads();

        for (int it = 0; it < 8; it++) {
            int r = it * 8 + warp;
            float sv[7];
            float mx = -1e30f;
            #pragma unroll
            for (int j = 0; j < 7; j++) {
                int col = lane + 32 * j;
                sv[j] = Ss[r * 232 + col] * 0.125f;
                if (col < MKV) mx = fmaxf(mx, sv[j]);
            }
            #pragma unroll
            for (int o = 16; o > 0; o >>= 1) mx = fmaxf(mx, __shfl_xor_sync(~0u, mx, o));
            float sum = 0.f;
            float pr[7];
            #pragma unroll
            for (int j = 0; j < 7; j++) {
                int col = lane + 32 * j;
                pr[j] = (col < MKV) ? __expf(sv[j] - mx) : 0.f;
                sum += pr[j];
            }
            #pragma unroll
            for (int o = 16; o > 0; o >>= 1) sum += __shfl_xor_sync(~0u, sum, o);
            float inv = 1.f / sum;
            #pragma unroll
            for (int j = 0; j < 7; j++) {
                int col = lane + 32 * j;
                Ps[r * 240 + col] = __float2half(pr[j] * inv);
            }
        }
        __syncthreads();

        {
            int mr = warp >> 1;
            int nc = warp & 1;
            wmma::fragment<wmma::accumulator, 16, 16, 16, float> oacc[2];
            #pragma unroll
            for (int j = 0; j < 2; j++) wmma::fill_fragment(oacc[j], 0.f);
            #pragma unroll
            for (int k = 0; k < 14; k++) {
                wmma::fragment<wmma::matrix_a, 16, 16, 16, __half, wmma::row_major> af;
                wmma::load_matrix_sync(af, &Ps[(mr * 16) * 240 + k * 16], 240);
                #pragma unroll
                for (int j = 0; j < 2; j++) {
                    wmma::fragment<wmma::matrix_b, 16, 16, 16, __half, wmma::row_major> bf;
                    wmma::load_matrix_sync(bf, &vs[(k * 16) * 80 + (nc * 2 + j) * 16], 80);
                    wmma::mma_sync(oacc[j], af, bf, oacc[j]);
                }
            }
            float* Es = Ss + warp * 384;
            #pragma unroll
            for (int j = 0; j < 2; j++) {
                wmma::store_matrix_sync(Es, oacc[j], 24, wmma::mem_row_major);
                __syncwarp();
                #pragma unroll
                for (int e = 0; e < 8; e++) {
                    int idx = lane + e * 32;
                    int r = idx >> 4;
                    int c = idx & 15;
                    int m = n0 + qt * 64 + mr * 16 + r;
                    int n = (nc * 2 + j) * 16 + c;
                    if (m < NN)
                        cat[((long)(b * NN + m)) * 640 + h * 64 + n] = __float2half(Es[r * 24 + c]);
                }
                __syncwarp();
            }
        }
        __syncthreads();
    }
}

// ---------------- launch ----------------
extern "C" void kernel_launch(void* const* d_in, const int* in_sizes, int n_in,
                              void* d_out, int out_size) {
    const float* x           = (const float*)d_in[0];
    const float* reduce_w    = (const float*)d_in[3];
    const float* reduce_b    = (const float*)d_in[4];
    const float* reduce_g    = (const float*)d_in[5];
    const float* reduce_beta = (const float*)d_in[6];
    const float* filter_w    = (const float*)d_in[7];
    const float* filter_b    = (const float*)d_in[8];
    const float* filter_g    = (const float*)d_in[9];
    const float* filter_beta = (const float*)d_in[10];
    const float* q_w         = (const float*)d_in[11];
    const float* q_b         = (const float*)d_in[12];
    const float* ln_g        = (const float*)d_in[13];
    const float* ln_b        = (const float*)d_in[14];
    const float* kv_w        = (const float*)d_in[15];
    const float* kv_b        = (const float*)d_in[16];
    const float* kve_w       = (const float*)d_in[17];
    const float* kve_b       = (const float*)d_in[18];
    const float* proj_w      = (const float*)d_in[19];
    const float* proj_b      = (const float*)d_in[20];
    float* out = (float*)d_out;

    __half *xh, *qh, *dwtbuf, *c3, *kvinh, *kvh, *cath;
    __half *qwh, *rwh, *fwh, *kvewh, *kvwh, *pwh;
    float *rtmp, *kvin;
    cudaGetSymbolAddress((void**)&xh,    g_xh);
    cudaGetSymbolAddress((void**)&qh,    g_qh);
    cudaGetSymbolAddress((void**)&rtmp,  g_rtmp);
    cudaGetSymbolAddress((void**)&dwtbuf,g_dwt);
    cudaGetSymbolAddress((void**)&c3,    g_c3);
    cudaGetSymbolAddress((void**)&kvin,  g_kvin);
    cudaGetSymbolAddress((void**)&kvinh, g_kvinh);
    cudaGetSymbolAddress((void**)&kvh,   g_kvh);
    cudaGetSymbolAddress((void**)&cath,  g_cath);
    cudaGetSymbolAddress((void**)&qwh,   g_qwh);
    cudaGetSymbolAddress((void**)&rwh,   g_rwh);
    cudaGetSymbolAddress((void**)&fwh,   g_fwh);
    cudaGetSymbolAddress((void**)&kvewh, g_kvewh);
    cudaGetSymbolAddress((void**)&kvwh,  g_kvwh);
    cudaGetSymbolAddress((void**)&pwh,   g_pwh);

    static int inited = 0;
    static cudaStream_t s1;
    static cudaEvent_t evFork, evX, evQ, evW3, evW2, evKVW, evPW, evConv, evI;
    if (!inited) {
        cudaFuncSetAttribute(gemm16<float>, cudaFuncAttributeMaxDynamicSharedMemorySize, GEMM_SMEM);
        cudaFuncSetAttribute(gemm16<__half>, cudaFuncAttributeMaxDynamicSharedMemorySize, GEMM_SMEM);
        cudaFuncSetAttribute(gemm16_64<float>, cudaFuncAttributeMaxDynamicSharedMemorySize, GEMM64_SMEM);
        cudaFuncSetAttribute(gemm16_64<__half>, cudaFuncAttributeMaxDynamicSharedMemorySize, GEMM64_SMEM);
        cudaFuncSetAttribute(conv3_g, cudaFuncAttributeMaxDynamicSharedMemorySize, GEMM64_SMEM);
        cudaFuncSetAttribute(kve_g, cudaFuncAttributeMaxDynamicSharedMemorySize, GEMM64_SMEM);
        cudaFuncSetAttribute(attn_w, cudaFuncAttributeMaxDynamicSharedMemorySize, ATTN_SMEM);
        cudaStreamCreateWithFlags(&s1, cudaStreamNonBlocking);
        cudaEventCreateWithFlags(&evFork, cudaEventDisableTiming);
        cudaEventCreateWithFlags(&evX,    cudaEventDisableTiming);
        cudaEventCreateWithFlags(&evQ,    cudaEventDisableTiming);
        cudaEventCreateWithFlags(&evW3,   cudaEventDisableTiming);
        cudaEventCreateWithFlags(&evW2,   cudaEventDisableTiming);
        cudaEventCreateWithFlags(&evKVW,  cudaEventDisableTiming);
        cudaEventCreateWithFlags(&evPW,   cudaEventDisableTiming);
        cudaEventCreateWithFlags(&evConv, cudaEventDisableTiming);
        cudaEventCreateWithFlags(&evI,    cudaEventDisableTiming);
        inited = 1;
    }

    cudaStream_t s0 = 0;

    cudaEventRecord(evFork, s0);
    cudaStreamWaitEvent(s1, evFork, 0);

    // ---- s0 critical chain start ----
    f2h8<<<(MTOK * CC / 8 + 255) / 256, 256, 0, s0>>>(x, xh, MTOK * CC);
    cudaEventRecord(evX, s0);
    f2h8<<<(C4 * CC / 8 + 255) / 256, 256, 0, s0>>>(reduce_w, rwh, C4 * CC);
    gemm16_64<float><<<dim3(1, 392), 256, GEMM64_SMEM, s0>>>(xh, rwh, reduce_b, rtmp, MTOK, C4, CC, C4);
    dwt_k<<<(BB * C4 * P2 + 255) / 256, 256, 0, s0>>>(rtmp, reduce_g, reduce_beta, dwtbuf);

    // ---- s1 side branch: weight prep + q GEMM ----
    reorder_w3<<<(512 * 4608 + 255) / 256, 256, 0, s1>>>(filter_w, fwh);
    cudaEventRecord(evW3, s1);
    reorder_w2<<<(512 * 2048 + 255) / 256, 256, 0, s1>>>(kve_w, kvewh);
    cudaEventRecord(evW2, s1);
    f2h8<<<(2 * CC * CC / 8 + 255) / 256, 256, 0, s1>>>(kv_w, kvwh, 2 * CC * CC);
    cudaEventRecord(evKVW, s1);
    f2h8<<<(CC * (CC + C4) / 8 + 255) / 256, 256, 0, s1>>>(proj_w, pwh, CC * (CC + C4));
    cudaEventRecord(evPW, s1);
    f2h8<<<(CC * CC / 8 + 255) / 256, 256, 0, s1>>>(q_w, qwh, CC * CC);
    cudaStreamWaitEvent(s1, evX, 0);
    gemm16<__half><<<dim3(4, 196), 256, GEMM_SMEM, s1>>>(xh, qwh, q_b, qh, MTOK, CC, CC, CC);
    cudaEventRecord(evQ, s1);

    // ---- s0: conv3 (64-row tiles, 392 CTAs) ----
    cudaStreamWaitEvent(s0, evW3, 0);
    conv3_g<<<dim3(4, 98), 256, GEMM64_SMEM, s0>>>(dwtbuf, fwh, filter_b, filter_g, filter_beta, c3);
    cudaEventRecord(evConv, s0);

    // ---- s1: idwt ----
    cudaStreamWaitEvent(s1, evConv, 0);
    idwt_k<<<(BB * C4 * P2 + 255) / 256, 256, 0, s1>>>(c3, cath);
    cudaEventRecord(evI, s1);

    // ---- s0: kve -> LN -> kv -> attn ----
    cudaStreamWaitEvent(s0, evW2, 0);
    kve_g<<<dim3(4, 25), 256, GEMM64_SMEM, s0>>>(c3, kvewh, kve_b, kvin);
    layernorm_k<<<BB * MKV, 512, 0, s0>>>(kvin, ln_g, ln_b, kvinh);
    cudaStreamWaitEvent(s0, evKVW, 0);
    gemm16_64<__half><<<dim3(8, 25), 256, GEMM64_SMEM, s0>>>(kvinh, kvwh, kv_b, kvh, BB * MKV, 2 * CC, CC, 2 * CC);
    cudaStreamWaitEvent(s0, evQ, 0);
    attn_w<<<dim3(BB * NHEADS, 13), 256, ATTN_SMEM, s0>>>(qh, kvh, cath);

    // ---- s0: proj ----
    cudaStreamWaitEvent(s0, evI, 0);
    cudaStreamWaitEvent(s0, evPW, 0);
    gemm16<float><<<dim3(4, 196), 256, GEMM_SMEM, s0>>>(cath, pwh, proj_b, out, MTOK, CC, CC + C4, CC);
}

// round 16
// speedup vs baseline: 1.0462x; 1.0462x over previous
#include <cuda_runtime.h>
#include <cuda_fp16.h>
#include <mma.h>
#include <cstdint>
using namespace nvcuda;

#define BB 8
#define NN 3136
#define CC 512
#define C4 128
#define NHEADS 8
#define P2 784
#define MKV 196
#define MTOK (BB*NN)

// ---------------- scratch ----------------
__device__ __half g_xh  [MTOK*CC];
__device__ __half g_qh  [MTOK*CC];
__device__ float  g_rtmp[MTOK*C4];
__device__ __half g_dwt [BB*P2*CC];       // NHWC
__device__ __half g_c3  [BB*P2*CC];       // NHWC
__device__ float  g_kvin[BB*MKV*CC];
__device__ __half g_kvinh[BB*MKV*CC];
__device__ __half g_kvh [BB*MKV*2*CC];
__device__ __half g_cath[MTOK*(CC+C4)];
__device__ __half g_wcomb[(CC+C4)*CC];    // [q_w ; reduce_w] fp16
__device__ __half g_fwh  [CC*CC*9];       // [oc][kyx][ic]
__device__ __half g_kvewh[CC*CC*4];       // [oc][kyx][ic]
__device__ __half g_kvwh [2*CC*CC];
__device__ __half g_pwh  [CC*(CC+C4)];

// ---------------- cp.async helpers ----------------
__device__ __forceinline__ unsigned int s2u(const void* p) {
    return (unsigned int)__cvta_generic_to_shared(p);
}
__device__ __forceinline__ void cp16(unsigned int d, const void* s) {
    asm volatile("cp.async.cg.shared.global [%0], [%1], 16;" :: "r"(d), "l"(s) : "memory");
}
__device__ __forceinline__ void cp16p(unsigned int d, const void* s, bool pred) {
    int sz = pred ? 16 : 0;
    asm volatile("cp.async.cg.shared.global [%0], [%1], 16, %2;" :: "r"(d), "l"(s), "r"(sz) : "memory");
}
__device__ __forceinline__ void cpcommit() { asm volatile("cp.async.commit_group;" ::: "memory"); }
__device__ __forceinline__ void cpwait0() { asm volatile("cp.async.wait_group 0;" ::: "memory"); }
__device__ __forceinline__ void cpwait1() { asm volatile("cp.async.wait_group 1;" ::: "memory"); }

// ---------------- conversion kernels ----------------
__global__ void f2h8(const float* __restrict__ s, __half* __restrict__ d, int n) {
    int i = (blockIdx.x * blockDim.x + threadIdx.x) * 8;
    if (i >= n) return;
    float4 a = *(const float4*)&s[i];
    float4 b = *(const float4*)&s[i + 4];
    __half2 h0 = __floats2half2_rn(a.x, a.y);
    __half2 h1 = __floats2half2_rn(a.z, a.w);
    __half2 h2 = __floats2half2_rn(b.x, b.y);
    __half2 h3 = __floats2half2_rn(b.z, b.w);
    uint4 o;
    o.x = *(unsigned int*)&h0;
    o.y = *(unsigned int*)&h1;
    o.z = *(unsigned int*)&h2;
    o.w = *(unsigned int*)&h3;
    *(uint4*)&d[i] = o;
}
__global__ void reorder_w3(const float* __restrict__ w, __half* __restrict__ o) {
    int idx = blockIdx.x * 256 + threadIdx.x;
    if (idx >= 512 * 4608) return;
    int oc = idx / 4608;
    int r = idx - oc * 4608;
    int kyx = r >> 9;
    int ic = r & 511;
    o[idx] = __float2half(w[((long)(oc * 512 + ic)) * 9 + kyx]);
}
__global__ void reorder_w2(const float* __restrict__ w, __half* __restrict__ o) {
    int idx = blockIdx.x * 256 + threadIdx.x;
    if (idx >= 512 * 2048) return;
    int oc = idx >> 11;
    int r = idx & 2047;
    int kyx = r >> 9;
    int ic = r & 511;
    o[idx] = __float2half(w[((long)(oc * 512 + ic)) * 4 + kyx]);
}

__device__ __forceinline__ void st_out(float* p, float v) { *p = v; }
__device__ __forceinline__ void st_out(__half* p, float v) { *p = __float2half(v); }

// =====================================================================
// gemm core 128x128, BK=64, 2-stage cp.async, 8 warps 64x32
// =====================================================================
#define GEMM_SMEM (2*128*72*2*2)
#define LDK 72
typedef wmma::fragment<wmma::accumulator, 16, 16, 16, float> AccFrag;

template<typename LT>
__device__ __forceinline__ void gemm_core(char* smem, int KT, LT loadTile,
                                          AccFrag (&acc)[4][2], int wr, int wc) {
    __half* As = (__half*)smem;
    __half* Bs = (__half*)(smem + 36864);
    #pragma unroll
    for (int i = 0; i < 4; i++)
        #pragma unroll
        for (int j = 0; j < 2; j++) wmma::fill_fragment(acc[i][j], 0.f);
    loadTile(0, 0); cpcommit();
    for (int kt = 0; kt < KT; kt++) {
        int cur = kt & 1;
        if (kt + 1 < KT) { loadTile(kt + 1, cur ^ 1); cpcommit(); cpwait1(); }
        else cpwait0();
        __syncthreads();
        #pragma unroll
        for (int kk = 0; kk < 64; kk += 16) {
            wmma::fragment<wmma::matrix_a, 16, 16, 16, __half, wmma::row_major> af[4];
            wmma::fragment<wmma::matrix_b, 16, 16, 16, __half, wmma::col_major> bf[2];
            #pragma unroll
            for (int i = 0; i < 4; i++)
                wmma::load_matrix_sync(af[i], &As[(cur * 128 + wr * 64 + i * 16) * LDK + kk], LDK);
            #pragma unroll
            for (int j = 0; j < 2; j++)
                wmma::load_matrix_sync(bf[j], &Bs[(cur * 128 + wc * 32 + j * 16) * LDK + kk], LDK);
            #pragma unroll
            for (int i = 0; i < 4; i++)
                #pragma unroll
                for (int j = 0; j < 2; j++)
                    wmma::mma_sync(acc[i][j], af[i], bf[j], acc[i][j]);
        }
        __syncthreads();
    }
}

// =====================================================================
// gemm core 64x128, BK=64, 2-stage, 8 warps 32x32 (wave-starved shapes)
// =====================================================================
#define GEMM64_SMEM (2*64*72*2 + 2*128*72*2)

template<typename LT>
__device__ __forceinline__ void gemm_core64(char* smem, int KT, LT loadTile,
                                            AccFrag (&acc)[2][2], int wm, int wn) {
    __half* As = (__half*)smem;
    __half* Bs = (__half*)(smem + 18432);
    #pragma unroll
    for (int i = 0; i < 2; i++)
        #pragma unroll
        for (int j = 0; j < 2; j++) wmma::fill_fragment(acc[i][j], 0.f);
    loadTile(0, 0); cpcommit();
    for (int kt = 0; kt < KT; kt++) {
        int cur = kt & 1;
        if (kt + 1 < KT) { loadTile(kt + 1, cur ^ 1); cpcommit(); cpwait1(); }
        else cpwait0();
        __syncthreads();
        #pragma unroll
        for (int kk = 0; kk < 64; kk += 16) {
            wmma::fragment<wmma::matrix_a, 16, 16, 16, __half, wmma::row_major> af[2];
            wmma::fragment<wmma::matrix_b, 16, 16, 16, __half, wmma::col_major> bf[2];
            #pragma unroll
            for (int i = 0; i < 2; i++)
                wmma::load_matrix_sync(af[i], &As[(cur * 64 + wm * 32 + i * 16) * LDK + kk], LDK);
            #pragma unroll
            for (int j = 0; j < 2; j++)
                wmma::load_matrix_sync(bf[j], &Bs[(cur * 128 + wn * 32 + j * 16) * LDK + kk], LDK);
            #pragma unroll
            for (int i = 0; i < 2; i++)
                #pragma unroll
                for (int j = 0; j < 2; j++)
                    wmma::mma_sync(acc[i][j], af[i], bf[j], acc[i][j]);
        }
        __syncthreads();
    }
}

// =====================================================================
// qr_gemm: fused q + reduce; A=xh, B=wcomb [640,512]; grid (5, 196)
// n<512 -> qh (fp16), n>=512 -> rtmp (fp32)
// =====================================================================
__global__ __launch_bounds__(256)
void qr_gemm(const __half* __restrict__ A, const __half* __restrict__ B,
             const float* __restrict__ qb, const float* __restrict__ rb,
             __half* __restrict__ qout, float* __restrict__ rout) {
    extern __shared__ char smem[];
    __half* As = (__half*)smem;
    __half* Bs = (__half*)(smem + 36864);
    float*  Es = (float*)smem;
    int tid = threadIdx.x;
    int warp = tid >> 5;
    int lane = tid & 31;
    int wr = warp & 1;
    int wc = warp >> 1;
    int m0 = blockIdx.y * 128;
    int n0 = blockIdx.x * 128;
    AccFrag acc[4][2];
    auto loadTile = [&](int kt, int buf) {
        int k0 = kt << 6;
        #pragma unroll
        for (int i = 0; i < 4; i++) {
            int c = tid + i * 256;
            int row = c >> 3;
            int off = (c & 7) * 8;
            cp16(s2u(&As[(buf * 128 + row) * LDK + off]), &A[((long)(m0 + row) << 9) + k0 + off]);
            cp16(s2u(&Bs[(buf * 128 + row) * LDK + off]), &B[((long)(n0 + row) << 9) + k0 + off]);
        }
    };
    gemm_core(smem, 8, loadTile, acc, wr, wc);
    __syncthreads();
    #pragma unroll
    for (int i = 0; i < 4; i++)
        #pragma unroll
        for (int j = 0; j < 2; j++) {
            wmma::store_matrix_sync(&Es[warp * 384], acc[i][j], 24, wmma::mem_row_major);
            __syncwarp();
            #pragma unroll
            for (int e = 0; e < 8; e++) {
                int idx = lane + e * 32;
                int r = idx >> 4;
                int c = idx & 15;
                int m = m0 + wr * 64 + i * 16 + r;
                int n = n0 + wc * 32 + j * 16 + c;
                float v = Es[warp * 384 + r * 24 + c];
                if (n < CC) qout[((long)m << 9) + n] = __float2half(v + qb[n]);
                else        rout[(long)m * C4 + (n - CC)] = v + rb[n - CC];
            }
            __syncwarp();
        }
}

// =====================================================================
// gemm16: 128x128 core (proj)
// =====================================================================
template<typename OT>
__global__ __launch_bounds__(256)
void gemm16(const __half* __restrict__ A, const __half* __restrict__ B,
            const float* __restrict__ bias, OT* __restrict__ C,
            int M, int N, int K, int ldc) {
    extern __shared__ char smem[];
    __half* As = (__half*)smem;
    __half* Bs = (__half*)(smem + 36864);
    float*  Es = (float*)smem;
    int tid = threadIdx.x;
    int warp = tid >> 5;
    int lane = tid & 31;
    int wr = warp & 1;
    int wc = warp >> 1;
    int m0 = blockIdx.y * 128;
    int n0 = blockIdx.x * 128;
    AccFrag acc[4][2];
    auto loadTile = [&](int kt, int buf) {
        int k0 = kt << 6;
        #pragma unroll
        for (int i = 0; i < 4; i++) {
            int c = tid + i * 256;
            int row = c >> 3;
            int off = (c & 7) * 8;
            int m = m0 + row;
            bool ok = (m < M);
            cp16p(s2u(&As[(buf * 128 + row) * LDK + off]), &A[(long)(ok ? m : 0) * K + k0 + off], ok);
            cp16(s2u(&Bs[(buf * 128 + row) * LDK + off]), &B[(long)(n0 + row) * K + k0 + off]);
        }
    };
    gemm_core(smem, K >> 6, loadTile, acc, wr, wc);
    __syncthreads();
    #pragma unroll
    for (int i = 0; i < 4; i++)
        #pragma unroll
        for (int j = 0; j < 2; j++) {
            wmma::store_matrix_sync(&Es[warp * 384], acc[i][j], 24, wmma::mem_row_major);
            __syncwarp();
            #pragma unroll
            for (int e = 0; e < 8; e++) {
                int idx = lane + e * 32;
                int r = idx >> 4;
                int c = idx & 15;
                int m = m0 + wr * 64 + i * 16 + r;
                int n = n0 + wc * 32 + j * 16 + c;
                if (m < M) st_out(&C[(long)m * ldc + n], Es[warp * 384 + r * 24 + c] + bias[n]);
            }
            __syncwarp();
        }
}

// =====================================================================
// gemm16_64: 64x128 core (kv)
// =====================================================================
template<typename OT>
__global__ __launch_bounds__(256)
void gemm16_64(const __half* __restrict__ A, const __half* __restrict__ B,
               const float* __restrict__ bias, OT* __restrict__ C,
               int M, int N, int K, int ldc) {
    extern __shared__ char smem[];
    __half* As = (__half*)smem;
    __half* Bs = (__half*)(smem + 18432);
    float*  Es = (float*)smem;
    int tid = threadIdx.x;
    int warp = tid >> 5;
    int lane = tid & 31;
    int wm = warp >> 2;
    int wn = warp & 3;
    int m0 = blockIdx.y * 64;
    int n0 = blockIdx.x * 128;
    AccFrag acc[2][2];
    auto loadTile = [&](int kt, int buf) {
        int k0 = kt << 6;
        #pragma unroll
        for (int i = 0; i < 2; i++) {
            int c = tid + i * 256;
            int row = c >> 3;
            int off = (c & 7) * 8;
            int m = m0 + row;
            bool ok = (m < M);
            cp16p(s2u(&As[(buf * 64 + row) * LDK + off]), &A[(long)(ok ? m : 0) * K + k0 + off], ok);
        }
        #pragma unroll
        for (int i = 0; i < 4; i++) {
            int c = tid + i * 256;
            int row = c >> 3;
            int off = (c & 7) * 8;
            cp16(s2u(&Bs[(buf * 128 + row) * LDK + off]), &B[(long)(n0 + row) * K + k0 + off]);
        }
    };
    gemm_core64(smem, K >> 6, loadTile, acc, wm, wn);
    __syncthreads();
    #pragma unroll
    for (int i = 0; i < 2; i++)
        #pragma unroll
        for (int j = 0; j < 2; j++) {
            wmma::store_matrix_sync(&Es[warp * 384], acc[i][j], 24, wmma::mem_row_major);
            __syncwarp();
            #pragma unroll
            for (int e = 0; e < 8; e++) {
                int idx = lane + e * 32;
                int r = idx >> 4;
                int c = idx & 15;
                int m = m0 + wm * 32 + i * 16 + r;
                int n = n0 + wn * 32 + j * 16 + c;
                if (m < M) st_out(&C[(long)m * ldc + n], Es[warp * 384 + r * 24 + c] + bias[n]);
            }
            __syncwarp();
        }
}

// =====================================================================
// conv3x3 implicit GEMM (NHWC), 64x128 tiles; M=6272,N=512,K=4608
// =====================================================================
__global__ __launch_bounds__(256)
void conv3_g(const __half* __restrict__ dwt, const __half* __restrict__ w,
             const float* __restrict__ cb, const float* __restrict__ cg,
             const float* __restrict__ cbeta, __half* __restrict__ out) {
    extern __shared__ char smem[];
    float* Es = (float*)smem;
    int tid = threadIdx.x;
    int warp = tid >> 5;
    int lane = tid & 31;
    int wm = warp >> 2;
    int wn = warp & 3;
    int m0 = blockIdx.y * 64;
    int n0 = blockIdx.x * 128;
    __half* As = (__half*)smem;
    __half* Bs = (__half*)(smem + 18432);
    int pre_b[2], pre_y[2], pre_x[2];
    #pragma unroll
    for (int i = 0; i < 2; i++) {
        int c = tid + i * 256;
        int row = c >> 3;
        int m = m0 + row;
        int b = m / P2;
        int p = m - b * P2;
        pre_b[i] = b;
        pre_y[i] = p / 28;
        pre_x[i] = p - (p / 28) * 28;
    }
    AccFrag acc[2][2];
    auto loadTile = [&](int kt, int buf) {
        int k0 = kt << 6;
        #pragma unroll
        for (int i = 0; i < 2; i++) {
            int c = tid + i * 256;
            int row = c >> 3;
            int off = (c & 7) * 8;
            int k = k0 + off;
            int kyx = k >> 9;
            int ic = k & 511;
            int ky = kyx / 3;
            int kx = kyx - ky * 3;
            int iy = pre_y[i] + ky - 1;
            int ix = pre_x[i] + kx - 1;
            bool ok = (iy >= 0 && iy < 28 && ix >= 0 && ix < 28);
            int iyc = ok ? iy : 0;
            int ixc = ok ? ix : 0;
            cp16p(s2u(&As[(buf * 64 + row) * LDK + off]),
                  &dwt[((long)(pre_b[i] * P2 + iyc * 28 + ixc) << 9) + ic], ok);
        }
        #pragma unroll
        for (int i = 0; i < 4; i++) {
            int c = tid + i * 256;
            int row = c >> 3;
            int off = (c & 7) * 8;
            cp16(s2u(&Bs[(buf * 128 + row) * LDK + off]), &w[(long)(n0 + row) * 4608 + k0 + off]);
        }
    };
    gemm_core64(smem, 72, loadTile, acc, wm, wn);
    __syncthreads();
    const float invs = rsqrtf(1.f + 1e-5f);
    #pragma unroll
    for (int i = 0; i < 2; i++)
        #pragma unroll
        for (int j = 0; j < 2; j++) {
            wmma::store_matrix_sync(&Es[warp * 384], acc[i][j], 24, wmma::mem_row_major);
            __syncwarp();
            #pragma unroll
            for (int e = 0; e < 8; e++) {
                int idx = lane + e * 32;
                int r = idx >> 4;
                int c = idx & 15;
                int m = m0 + wm * 32 + i * 16 + r;
                int n = n0 + wn * 32 + j * 16 + c;
                float v = Es[warp * 384 + r * 24 + c] + cb[n];
                v = v * (cg[n] * invs) + cbeta[n];
                out[((long)m << 9) + n] = __float2half(fmaxf(v, 0.f));
            }
            __syncwarp();
        }
}

// =====================================================================
// kve 2x2 s2 conv implicit GEMM, 64x128 tiles; M=1568,N=512,K=2048
// =====================================================================
__global__ __launch_bounds__(256)
void kve_g(const __half* __restrict__ c3, const __half* __restrict__ w,
           const float* __restrict__ bias, float* __restrict__ out) {
    extern __shared__ char smem[];
    float* Es = (float*)smem;
    int tid = threadIdx.x;
    int warp = tid >> 5;
    int lane = tid & 31;
    int wm = warp >> 2;
    int wn = warp & 3;
    int m0 = blockIdx.y * 64;
    int n0 = blockIdx.x * 128;
    __half* As = (__half*)smem;
    __half* Bs = (__half*)(smem + 18432);
    int pre_s[2];
    bool pre_v[2];
    #pragma unroll
    for (int i = 0; i < 2; i++) {
        int c = tid + i * 256;
        int row = c >> 3;
        int m = m0 + row;
        pre_v[i] = (m < BB * MKV);
        int mm = pre_v[i] ? m : 0;
        int b = mm / MKV;
        int p = mm - b * MKV;
        int oy = p / 14;
        int ox = p - (p / 14) * 14;
        pre_s[i] = b * P2 + 2 * oy * 28 + 2 * ox;
    }
    AccFrag acc[2][2];
    auto loadTile = [&](int kt, int buf) {
        int k0 = kt << 6;
        #pragma unroll
        for (int i = 0; i < 2; i++) {
            int c = tid + i * 256;
            int row = c >> 3;
            int off = (c & 7) * 8;
            int k = k0 + off;
            int kyx = k >> 9;
            int ic = k & 511;
            int ky = kyx >> 1;
            int kx = kyx & 1;
            cp16p(s2u(&As[(buf * 64 + row) * LDK + off]),
                  &c3[((long)(pre_s[i] + ky * 28 + kx) << 9) + ic], pre_v[i]);
        }
        #pragma unroll
        for (int i = 0; i < 4; i++) {
            int c = tid + i * 256;
            int row = c >> 3;
            int off = (c & 7) * 8;
            cp16(s2u(&Bs[(buf * 128 + row) * LDK + off]), &w[(long)(n0 + row) * 2048 + k0 + off]);
        }
    };
    gemm_core64(smem, 32, loadTile, acc, wm, wn);
    __syncthreads();
    #pragma unroll
    for (int i = 0; i < 2; i++)
        #pragma unroll
        for (int j = 0; j < 2; j++) {
            wmma::store_matrix_sync(&Es[warp * 384], acc[i][j], 24, wmma::mem_row_major);
            __syncwarp();
            #pragma unroll
            for (int e = 0; e < 8; e++) {
                int idx = lane + e * 32;
                int r = idx >> 4;
                int c = idx & 15;
                int m = m0 + wm * 32 + i * 16 + r;
                int n = n0 + wn * 32 + j * 16 + c;
                if (m < BB * MKV) out[(long)m * CC + n] = Es[warp * 384 + r * 24 + c] + bias[n];
            }
            __syncwarp();
        }
}

// ---------------- BN+ReLU+fp16+DWT ----------------
__global__ void dwt_k(const float* __restrict__ rtmp, const float* __restrict__ g,
                      const float* __restrict__ beta, __half* __restrict__ dwt) {
    int idx = blockIdx.x * blockDim.x + threadIdx.x;
    if (idx >= BB * C4 * P2) return;
    int c = idx & 127;
    int p = (idx >> 7) % P2;
    int b = idx / (C4 * P2);
    int y2 = p / 28;
    int x2 = p % 28;
    float s = g[c] * rsqrtf(1.f + 1e-5f);
    float bt = beta[c];
    const __half hhalf = __float2half(0.5f);
    __half xh[2][2];
    #pragma unroll
    for (int dy = 0; dy < 2; dy++)
        #pragma unroll
        for (int dx = 0; dx < 2; dx++) {
            int n = (2 * y2 + dy) * 56 + (2 * x2 + dx);
            float v = rtmp[((long)(b * NN + n)) * C4 + c];
            v = fmaxf(v * s + bt, 0.f);
            xh[dy][dx] = __hmul(__float2half(v), hhalf);
        }
    __half x1 = xh[0][0], x2h = xh[1][0], x3 = xh[0][1], x4 = xh[1][1];
    __half ll = __hadd(__hadd(__hadd(x1, x2h), x3), x4);
    __half hl = __hadd(__hadd(__hsub(__hneg(x1), x2h), x3), x4);
    __half lh = __hadd(__hsub(__hadd(__hneg(x1), x2h), x3), x4);
    __half hh = __hadd(__hsub(__hsub(x1, x2h), x3), x4);
    long base = ((long)(b * P2 + p) << 9) + c;
    dwt[base]       = ll;
    dwt[base + 128] = hl;
    dwt[base + 256] = lh;
    dwt[base + 384] = hh;
}

// ---------------- IDWT -> cath[:, 512:] ----------------
__global__ void idwt_k(const __half* __restrict__ c3, __half* __restrict__ cat) {
    int idx = blockIdx.x * blockDim.x + threadIdx.x;
    if (idx >= BB * C4 * P2) return;
    int c = idx & 127;
    int p = (idx >> 7) % P2;
    int b = idx / (C4 * P2);
    int y2 = p / 28;
    int x2 = p % 28;
    long base = ((long)(b * P2 + p) << 9) + c;
    __half ll = c3[base], hl = c3[base + 128], lh = c3[base + 256], hh = c3[base + 384];
    const __half hhalf = __float2half(0.5f);
    __half p1 = __hmul(__hadd(__hsub(__hsub(ll, hl), lh), hh), hhalf);
    __half p2 = __hmul(__hsub(__hadd(__hsub(ll, hl), lh), hh), hhalf);
    __half p3 = __hmul(__hsub(__hsub(__hadd(ll, hl), lh), hh), hhalf);
    __half p4 = __hmul(__hadd(__hadd(__hadd(ll, hl), lh), hh), hhalf);
    int n00 = (2 * y2) * 56 + 2 * x2;
    long cb = ((long)(b * NN)) * 640 + 512 + c;
    cat[cb + (long)n00 * 640]        = p1;
    cat[cb + (long)(n00 + 1) * 640]  = p3;
    cat[cb + (long)(n00 + 56) * 640] = p2;
    cat[cb + (long)(n00 + 57) * 640] = p4;
}

// ---------------- LayerNorm ----------------
__global__ void layernorm_k(const float* __restrict__ buf, const float* __restrict__ g,
                            const float* __restrict__ bta, __half* __restrict__ outh) {
    int row = blockIdx.x;
    const float* p = buf + (long)row * CC;
    __shared__ float red[16];
    int tid = threadIdx.x;
    float v = p[tid];
    float s = v;
    #pragma unroll
    for (int o = 16; o > 0; o >>= 1) s += __shfl_xor_sync(~0u, s, o);
    if ((tid & 31) == 0) red[tid >> 5] = s;
    __syncthreads();
    if (tid < 16) {
        float t = red[tid];
        #pragma unroll
        for (int o = 8; o > 0; o >>= 1) t += __shfl_xor_sync(0xffffu, t, o);
        if (tid == 0) red[0] = t;
    }
    __syncthreads();
    float mu = red[0] * (1.f / 512.f);
    __syncthreads();
    float d = v - mu;
    float s2 = d * d;
    #pragma unroll
    for (int o = 16; o > 0; o >>= 1) s2 += __shfl_xor_sync(~0u, s2, o);
    if ((tid & 31) == 0) red[tid >> 5] = s2;
    __syncthreads();
    if (tid < 16) {
        float t = red[tid];
        #pragma unroll
        for (int o = 8; o > 0; o >>= 1) t += __shfl_xor_sync(0xffffu, t, o);
        if (tid == 0) red[0] = t;
    }
    __syncthreads();
    float var = red[0] * (1.f / 512.f);
    outh[(long)row * CC + tid] = __float2half(d * (1.f / sqrtf(var + 1e-5f)) * g[tid] + bta[tid]);
}

// =====================================================================
// WMMA attention, 128 q rows per block (2 x 64-row subtiles share K/V)
// =====================================================================
#define ATTN_SMEM (128*80*2 + 224*80*2*2 + 64*240*2 + 64*232*4)
__global__ __launch_bounds__(256)
void attn_w(const __half* __restrict__ qh, const __half* __restrict__ kvh,
            __half* __restrict__ cat) {
    extern __shared__ char smem[];
    __half* qs  = (__half*)smem;
    __half* ks  = (__half*)(smem + 20480);
    __half* vs  = (__half*)(smem + 20480 + 35840);
    __half* Ps  = (__half*)(smem + 20480 + 71680);
    float*  Ss  = (float*)(smem + 20480 + 71680 + 30720);
    int b = blockIdx.x >> 3;
    int h = blockIdx.x & 7;
    int n0 = blockIdx.y * 128;
    int nsub = (n0 + 64 < NN) ? 2 : 1;
    int tid = threadIdx.x;
    int warp = tid >> 5;
    int lane = tid & 31;

    #pragma unroll
    for (int i = 0; i < 4; i++) {
        int c = tid + i * 256;
        int row = c >> 3;
        int off = (c & 7) * 8;
        bool ok = (n0 + row < NN);
        int rowc = ok ? row : 0;
        cp16p(s2u(&qs[row * 80 + off]), &qh[((long)(b * NN + n0 + rowc) << 9) + h * 64 + off], ok);
    }
    #pragma unroll
    for (int i = 0; i < 7; i++) {
        int c = tid + i * 256;
        int row = c >> 3;
        int off = (c & 7) * 8;
        bool ok = row < MKV;
        int rc = ok ? row : 0;
        const __half* base = &kvh[((long)(b * MKV + rc) << 10) + h * 64 + off];
        cp16p(s2u(&ks[row * 80 + off]), base, ok);
        cp16p(s2u(&vs[row * 80 + off]), base + 512, ok);
    }
    cpcommit(); cpwait0();
    __syncthreads();

    for (int qt = 0; qt < nsub; qt++) {
        __half* qsub = qs + qt * 64 * 80;
        {
            int mr = warp >> 1;
            int nh = warp & 1;
            wmma::fragment<wmma::accumulator, 16, 16, 16, float> sacc[7];
            #pragma unroll
            for (int j = 0; j < 7; j++) wmma::fill_fragment(sacc[j], 0.f);
            #pragma unroll
            for (int kk = 0; kk < 64; kk += 16) {
                wmma::fragment<wmma::matrix_a, 16, 16, 16, __half, wmma::row_major> af;
                wmma::load_matrix_sync(af, &qsub[(mr * 16) * 80 + kk], 80);
                #pragma unroll
                for (int j = 0; j < 7; j++) {
                    wmma::fragment<wmma::matrix_b, 16, 16, 16, __half, wmma::col_major> bf;
                    wmma::load_matrix_sync(bf, &ks[((nh * 7 + j) * 16) * 80 + kk], 80);
                    wmma::mma_sync(sacc[j], af, bf, sacc[j]);
                }
            }
            #pragma unroll
            for (int j = 0; j < 7; j++)
                wmma::store_matrix_sync(&Ss[(mr * 16) * 232 + (nh * 7 + j) * 16], sacc[j], 232,
                                        wmma::mem_row_major);
        }
        __syncthreads();

        for (int it = 0; it < 8; it++) {
            int r = it * 8 + warp;
            float sv[7];
            float mx = -1e30f;
            #pragma unroll
            for (int j = 0; j < 7; j++) {
                int col = lane + 32 * j;
                sv[j] = Ss[r * 232 + col] * 0.125f;
                if (col < MKV) mx = fmaxf(mx, sv[j]);
            }
            #pragma unroll
            for (int o = 16; o > 0; o >>= 1) mx = fmaxf(mx, __shfl_xor_sync(~0u, mx, o));
            float sum = 0.f;
            float pr[7];
            #pragma unroll
            for (int j = 0; j < 7; j++) {
                int col = lane + 32 * j;
                pr[j] = (col < MKV) ? __expf(sv[j] - mx) : 0.f;
                sum += pr[j];
            }
            #pragma unroll
            for (int o = 16; o > 0; o >>= 1) sum += __shfl_xor_sync(~0u, sum, o);
            float inv = 1.f / sum;
            #pragma unroll
            for (int j = 0; j < 7; j++) {
                int col = lane + 32 * j;
                Ps[r * 240 + col] = __float2half(pr[j] * inv);
            }
        }
        __syncthreads();

        {
            int mr = warp >> 1;
            int nc = warp & 1;
            wmma::fragment<wmma::accumulator, 16, 16, 16, float> oacc[2];
            #pragma unroll
            for (int j = 0; j < 2; j++) wmma::fill_fragment(oacc[j], 0.f);
            #pragma unroll
            for (int k = 0; k < 14; k++) {
                wmma::fragment<wmma::matrix_a, 16, 16, 16, __half, wmma::row_major> af;
                wmma::load_matrix_sync(af, &Ps[(mr * 16) * 240 + k * 16], 240);
                #pragma unroll
                for (int j = 0; j < 2; j++) {
                    wmma::fragment<wmma::matrix_b, 16, 16, 16, __half, wmma::row_major> bf;
                    wmma::load_matrix_sync(bf, &vs[(k * 16) * 80 + (nc * 2 + j) * 16], 80);
                    wmma::mma_sync(oacc[j], af, bf, oacc[j]);
                }
            }
            float* Es = Ss + warp * 384;
            #pragma unroll
            for (int j = 0; j < 2; j++) {
                wmma::store_matrix_sync(Es, oacc[j], 24, wmma::mem_row_major);
                __syncwarp();
                #pragma unroll
                for (int e = 0; e < 8; e++) {
                    int idx = lane + e * 32;
                    int r = idx >> 4;
                    int c = idx & 15;
                    int m = n0 + qt * 64 + mr * 16 + r;
                    int n = (nc * 2 + j) * 16 + c;
                    cat[((long)(b * NN + m)) * 640 + h * 64 + n] = __float2half(Es[r * 24 + c]);
                }
                __syncwarp();
            }
        }
        __syncthreads();
    }
}

// ---------------- launch ----------------
extern "C" void kernel_launch(void* const* d_in, const int* in_sizes, int n_in,
                              void* d_out, int out_size) {
    const float* x           = (const float*)d_in[0];
    const float* reduce_w    = (const float*)d_in[3];
    const float* reduce_b    = (const float*)d_in[4];
    const float* reduce_g    = (const float*)d_in[5];
    const float* reduce_beta = (const float*)d_in[6];
    const float* filter_w    = (const float*)d_in[7];
    const float* filter_b    = (const float*)d_in[8];
    const float* filter_g    = (const float*)d_in[9];
    const float* filter_beta = (const float*)d_in[10];
    const float* q_w         = (const float*)d_in[11];
    const float* q_b         = (const float*)d_in[12];
    const float* ln_g        = (const float*)d_in[13];
    const float* ln_b        = (const float*)d_in[14];
    const float* kv_w        = (const float*)d_in[15];
    const float* kv_b        = (const float*)d_in[16];
    const float* kve_w       = (const float*)d_in[17];
    const float* kve_b       = (const float*)d_in[18];
    const float* proj_w      = (const float*)d_in[19];
    const float* proj_b      = (const float*)d_in[20];
    float* out = (float*)d_out;

    __half *xh, *qh, *dwtbuf, *c3, *kvinh, *kvh, *cath;
    __half *wcomb, *fwh, *kvewh, *kvwh, *pwh;
    float *rtmp, *kvin;
    cudaGetSymbolAddress((void**)&xh,    g_xh);
    cudaGetSymbolAddress((void**)&qh,    g_qh);
    cudaGetSymbolAddress((void**)&rtmp,  g_rtmp);
    cudaGetSymbolAddress((void**)&dwtbuf,g_dwt);
    cudaGetSymbolAddress((void**)&c3,    g_c3);
    cudaGetSymbolAddress((void**)&kvin,  g_kvin);
    cudaGetSymbolAddress((void**)&kvinh, g_kvinh);
    cudaGetSymbolAddress((void**)&kvh,   g_kvh);
    cudaGetSymbolAddress((void**)&cath,  g_cath);
    cudaGetSymbolAddress((void**)&wcomb, g_wcomb);
    cudaGetSymbolAddress((void**)&fwh,   g_fwh);
    cudaGetSymbolAddress((void**)&kvewh, g_kvewh);
    cudaGetSymbolAddress((void**)&kvwh,  g_kvwh);
    cudaGetSymbolAddress((void**)&pwh,   g_pwh);

    static int inited = 0;
    static cudaStream_t s1;
    static cudaEvent_t evFork, evQW, evW3, evW2, evKVW, evPW, evConv, evI;
    if (!inited) {
        cudaFuncSetAttribute(qr_gemm, cudaFuncAttributeMaxDynamicSharedMemorySize, GEMM_SMEM);
        cudaFuncSetAttribute(gemm16<float>, cudaFuncAttributeMaxDynamicSharedMemorySize, GEMM_SMEM);
        cudaFuncSetAttribute(gemm16_64<__half>, cudaFuncAttributeMaxDynamicSharedMemorySize, GEMM64_SMEM);
        cudaFuncSetAttribute(conv3_g, cudaFuncAttributeMaxDynamicSharedMemorySize, GEMM64_SMEM);
        cudaFuncSetAttribute(kve_g, cudaFuncAttributeMaxDynamicSharedMemorySize, GEMM64_SMEM);
        cudaFuncSetAttribute(attn_w, cudaFuncAttributeMaxDynamicSharedMemorySize, ATTN_SMEM);
        cudaStreamCreateWithFlags(&s1, cudaStreamNonBlocking);
        cudaEventCreateWithFlags(&evFork, cudaEventDisableTiming);
        cudaEventCreateWithFlags(&evQW,   cudaEventDisableTiming);
        cudaEventCreateWithFlags(&evW3,   cudaEventDisableTiming);
        cudaEventCreateWithFlags(&evW2,   cudaEventDisableTiming);
        cudaEventCreateWithFlags(&evKVW,  cudaEventDisableTiming);
        cudaEventCreateWithFlags(&evPW,   cudaEventDisableTiming);
        cudaEventCreateWithFlags(&evConv, cudaEventDisableTiming);
        cudaEventCreateWithFlags(&evI,    cudaEventDisableTiming);
        inited = 1;
    }

    cudaStream_t s0 = 0;

    cudaEventRecord(evFork, s0);
    cudaStreamWaitEvent(s1, evFork, 0);

    // ---- s1: weight prep ----
    f2h8<<<(CC * CC / 8 + 255) / 256, 256, 0, s1>>>(q_w, wcomb, CC * CC);
    f2h8<<<(C4 * CC / 8 + 255) / 256, 256, 0, s1>>>(reduce_w, wcomb + CC * CC, C4 * CC);
    cudaEventRecord(evQW, s1);
    reorder_w3<<<(512 * 4608 + 255) / 256, 256, 0, s1>>>(filter_w, fwh);
    cudaEventRecord(evW3, s1);
    reorder_w2<<<(512 * 2048 + 255) / 256, 256, 0, s1>>>(kve_w, kvewh);
    cudaEventRecord(evW2, s1);
    f2h8<<<(2 * CC * CC / 8 + 255) / 256, 256, 0, s1>>>(kv_w, kvwh, 2 * CC * CC);
    cudaEventRecord(evKVW, s1);
    f2h8<<<(CC * (CC + C4) / 8 + 255) / 256, 256, 0, s1>>>(proj_w, pwh, CC * (CC + C4));
    cudaEventRecord(evPW, s1);

    // ---- s0 critical chain ----
    f2h8<<<(MTOK * CC / 8 + 255) / 256, 256, 0, s0>>>(x, xh, MTOK * CC);
    cudaStreamWaitEvent(s0, evQW, 0);
    qr_gemm<<<dim3(5, 196), 256, GEMM_SMEM, s0>>>(xh, wcomb, q_b, reduce_b, qh, rtmp);
    dwt_k<<<(BB * C4 * P2 + 255) / 256, 256, 0, s0>>>(rtmp, reduce_g, reduce_beta, dwtbuf);
    cudaStreamWaitEvent(s0, evW3, 0);
    conv3_g<<<dim3(4, 98), 256, GEMM64_SMEM, s0>>>(dwtbuf, fwh, filter_b, filter_g, filter_beta, c3);
    cudaEventRecord(evConv, s0);

    // ---- s1: idwt ----
    cudaStreamWaitEvent(s1, evConv, 0);
    idwt_k<<<(BB * C4 * P2 + 255) / 256, 256, 0, s1>>>(c3, cath);
    cudaEventRecord(evI, s1);

    // ---- s0: kve -> LN -> kv -> attn ----
    cudaStreamWaitEvent(s0, evW2, 0);
    kve_g<<<dim3(4, 25), 256, GEMM64_SMEM, s0>>>(c3, kvewh, kve_b, kvin);
    layernorm_k<<<BB * MKV, 512, 0, s0>>>(kvin, ln_g, ln_b, kvinh);
    cudaStreamWaitEvent(s0, evKVW, 0);
    gemm16_64<__half><<<dim3(8, 25), 256, GEMM64_SMEM, s0>>>(kvinh, kvwh, kv_b, kvh, BB * MKV, 2 * CC, CC, 2 * CC);
    attn_w<<<dim3(BB * NHEADS, 25), 256, ATTN_SMEM, s0>>>(qh, kvh, cath);

    // ---- s0: proj ----
    cudaStreamWaitEvent(s0, evI, 0);
    cudaStreamWaitEvent(s0, evPW, 0);
    gemm16<float><<<dim3(4, 196), 256, GEMM_SMEM, s0>>>(cath, pwh, proj_b, out, MTOK, CC, CC + C4, CC);
}

// round 17
// speedup vs baseline: 1.0655x; 1.0185x over previous
#include <cuda_runtime.h>
#include <cuda_fp16.h>
#include <mma.h>
#include <cstdint>
using namespace nvcuda;

#define BB 8
#define NN 3136
#define CC 512
#define C4 128
#define NHEADS 8
#define P2 784
#define MKV 196
#define MTOK (BB*NN)

// ---------------- scratch ----------------
__device__ __half g_xh  [MTOK*CC];
__device__ __half g_qh  [MTOK*CC];
__device__ float  g_rtmp[MTOK*C4];
__device__ __half g_dwt [BB*P2*CC];       // NHWC
__device__ __half g_c3  [BB*P2*CC];       // NHWC
__device__ float  g_kvin[BB*MKV*CC];
__device__ __half g_kvinh[BB*MKV*CC];
__device__ __half g_kvh [BB*MKV*2*CC];
__device__ __half g_cath[MTOK*(CC+C4)];
__device__ __half g_wcomb[(CC+C4)*CC];    // [q_w ; reduce_w] fp16
__device__ __half g_fwh  [CC*CC*9];       // [oc][kyx][ic]
__device__ __half g_kvewh[CC*CC*4];       // [oc][kyx][ic]
__device__ __half g_kvwh [2*CC*CC];
__device__ __half g_pwh  [CC*(CC+C4)];

// ---------------- cp.async helpers ----------------
__device__ __forceinline__ unsigned int s2u(const void* p) {
    return (unsigned int)__cvta_generic_to_shared(p);
}
__device__ __forceinline__ void cp16(unsigned int d, const void* s) {
    asm volatile("cp.async.cg.shared.global [%0], [%1], 16;" :: "r"(d), "l"(s) : "memory");
}
__device__ __forceinline__ void cp16p(unsigned int d, const void* s, bool pred) {
    int sz = pred ? 16 : 0;
    asm volatile("cp.async.cg.shared.global [%0], [%1], 16, %2;" :: "r"(d), "l"(s), "r"(sz) : "memory");
}
__device__ __forceinline__ void cpcommit() { asm volatile("cp.async.commit_group;" ::: "memory"); }
__device__ __forceinline__ void cpwait0() { asm volatile("cp.async.wait_group 0;" ::: "memory"); }
__device__ __forceinline__ void cpwait1() { asm volatile("cp.async.wait_group 1;" ::: "memory"); }

// ---------------- conversion kernels ----------------
__global__ void f2h8(const float* __restrict__ s, __half* __restrict__ d, int n) {
    int i = (blockIdx.x * blockDim.x + threadIdx.x) * 8;
    if (i >= n) return;
    float4 a = *(const float4*)&s[i];
    float4 b = *(const float4*)&s[i + 4];
    __half2 h0 = __floats2half2_rn(a.x, a.y);
    __half2 h1 = __floats2half2_rn(a.z, a.w);
    __half2 h2 = __floats2half2_rn(b.x, b.y);
    __half2 h3 = __floats2half2_rn(b.z, b.w);
    uint4 o;
    o.x = *(unsigned int*)&h0;
    o.y = *(unsigned int*)&h1;
    o.z = *(unsigned int*)&h2;
    o.w = *(unsigned int*)&h3;
    *(uint4*)&d[i] = o;
}
__global__ void reorder_w3(const float* __restrict__ w, __half* __restrict__ o) {
    int idx = blockIdx.x * 256 + threadIdx.x;
    if (idx >= 512 * 4608) return;
    int oc = idx / 4608;
    int r = idx - oc * 4608;
    int kyx = r >> 9;
    int ic = r & 511;
    o[idx] = __float2half(w[((long)(oc * 512 + ic)) * 9 + kyx]);
}
__global__ void reorder_w2(const float* __restrict__ w, __half* __restrict__ o) {
    int idx = blockIdx.x * 256 + threadIdx.x;
    if (idx >= 512 * 2048) return;
    int oc = idx >> 11;
    int r = idx & 2047;
    int kyx = r >> 9;
    int ic = r & 511;
    o[idx] = __float2half(w[((long)(oc * 512 + ic)) * 4 + kyx]);
}

__device__ __forceinline__ void st_out(float* p, float v) { *p = v; }
__device__ __forceinline__ void st_out(__half* p, float v) { *p = __float2half(v); }

// =====================================================================
// gemm core 128x128, BK=64, 2-stage cp.async, 8 warps 64x32
// =====================================================================
#define GEMM_SMEM (2*128*72*2*2)
#define LDK 72
typedef wmma::fragment<wmma::accumulator, 16, 16, 16, float> AccFrag;

template<typename LT>
__device__ __forceinline__ void gemm_core(char* smem, int KT, LT loadTile,
                                          AccFrag (&acc)[4][2], int wr, int wc) {
    __half* As = (__half*)smem;
    __half* Bs = (__half*)(smem + 36864);
    #pragma unroll
    for (int i = 0; i < 4; i++)
        #pragma unroll
        for (int j = 0; j < 2; j++) wmma::fill_fragment(acc[i][j], 0.f);
    loadTile(0, 0); cpcommit();
    for (int kt = 0; kt < KT; kt++) {
        int cur = kt & 1;
        if (kt + 1 < KT) { loadTile(kt + 1, cur ^ 1); cpcommit(); cpwait1(); }
        else cpwait0();
        __syncthreads();
        #pragma unroll
        for (int kk = 0; kk < 64; kk += 16) {
            wmma::fragment<wmma::matrix_a, 16, 16, 16, __half, wmma::row_major> af[4];
            wmma::fragment<wmma::matrix_b, 16, 16, 16, __half, wmma::col_major> bf[2];
            #pragma unroll
            for (int i = 0; i < 4; i++)
                wmma::load_matrix_sync(af[i], &As[(cur * 128 + wr * 64 + i * 16) * LDK + kk], LDK);
            #pragma unroll
            for (int j = 0; j < 2; j++)
                wmma::load_matrix_sync(bf[j], &Bs[(cur * 128 + wc * 32 + j * 16) * LDK + kk], LDK);
            #pragma unroll
            for (int i = 0; i < 4; i++)
                #pragma unroll
                for (int j = 0; j < 2; j++)
                    wmma::mma_sync(acc[i][j], af[i], bf[j], acc[i][j]);
        }
        __syncthreads();
    }
}

// =====================================================================
// gemm core 64x128, BK=64, 2-stage, 8 warps 32x32 (wave-starved shapes)
// =====================================================================
#define GEMM64_SMEM (2*64*72*2 + 2*128*72*2)

template<typename LT>
__device__ __forceinline__ void gemm_core64(char* smem, int KT, LT loadTile,
                                            AccFrag (&acc)[2][2], int wm, int wn) {
    __half* As = (__half*)smem;
    __half* Bs = (__half*)(smem + 18432);
    #pragma unroll
    for (int i = 0; i < 2; i++)
        #pragma unroll
        for (int j = 0; j < 2; j++) wmma::fill_fragment(acc[i][j], 0.f);
    loadTile(0, 0); cpcommit();
    for (int kt = 0; kt < KT; kt++) {
        int cur = kt & 1;
        if (kt + 1 < KT) { loadTile(kt + 1, cur ^ 1); cpcommit(); cpwait1(); }
        else cpwait0();
        __syncthreads();
        #pragma unroll
        for (int kk = 0; kk < 64; kk += 16) {
            wmma::fragment<wmma::matrix_a, 16, 16, 16, __half, wmma::row_major> af[2];
            wmma::fragment<wmma::matrix_b, 16, 16, 16, __half, wmma::col_major> bf[2];
            #pragma unroll
            for (int i = 0; i < 2; i++)
                wmma::load_matrix_sync(af[i], &As[(cur * 64 + wm * 32 + i * 16) * LDK + kk], LDK);
            #pragma unroll
            for (int j = 0; j < 2; j++)
                wmma::load_matrix_sync(bf[j], &Bs[(cur * 128 + wn * 32 + j * 16) * LDK + kk], LDK);
            #pragma unroll
            for (int i = 0; i < 2; i++)
                #pragma unroll
                for (int j = 0; j < 2; j++)
                    wmma::mma_sync(acc[i][j], af[i], bf[j], acc[i][j]);
        }
        __syncthreads();
    }
}

// =====================================================================
// qr_gemm: fused q + reduce; A=xh, B=wcomb [640,512]; grid (5, 196)
// =====================================================================
__global__ __launch_bounds__(256)
void qr_gemm(const __half* __restrict__ A, const __half* __restrict__ B,
             const float* __restrict__ qb, const float* __restrict__ rb,
             __half* __restrict__ qout, float* __restrict__ rout) {
    extern __shared__ char smem[];
    __half* As = (__half*)smem;
    __half* Bs = (__half*)(smem + 36864);
    float*  Es = (float*)smem;
    int tid = threadIdx.x;
    int warp = tid >> 5;
    int lane = tid & 31;
    int wr = warp & 1;
    int wc = warp >> 1;
    int m0 = blockIdx.y * 128;
    int n0 = blockIdx.x * 128;
    AccFrag acc[4][2];
    auto loadTile = [&](int kt, int buf) {
        int k0 = kt << 6;
        #pragma unroll
        for (int i = 0; i < 4; i++) {
            int c = tid + i * 256;
            int row = c >> 3;
            int off = (c & 7) * 8;
            cp16(s2u(&As[(buf * 128 + row) * LDK + off]), &A[((long)(m0 + row) << 9) + k0 + off]);
            cp16(s2u(&Bs[(buf * 128 + row) * LDK + off]), &B[((long)(n0 + row) << 9) + k0 + off]);
        }
    };
    gemm_core(smem, 8, loadTile, acc, wr, wc);
    __syncthreads();
    #pragma unroll
    for (int i = 0; i < 4; i++)
        #pragma unroll
        for (int j = 0; j < 2; j++) {
            wmma::store_matrix_sync(&Es[warp * 384], acc[i][j], 24, wmma::mem_row_major);
            __syncwarp();
            #pragma unroll
            for (int e = 0; e < 8; e++) {
                int idx = lane + e * 32;
                int r = idx >> 4;
                int c = idx & 15;
                int m = m0 + wr * 64 + i * 16 + r;
                int n = n0 + wc * 32 + j * 16 + c;
                float v = Es[warp * 384 + r * 24 + c];
                if (n < CC) qout[((long)m << 9) + n] = __float2half(v + qb[n]);
                else        rout[(long)m * C4 + (n - CC)] = v + rb[n - CC];
            }
            __syncwarp();
        }
}

// =====================================================================
// gemm16: 128x128 core (proj)
// =====================================================================
template<typename OT>
__global__ __launch_bounds__(256)
void gemm16(const __half* __restrict__ A, const __half* __restrict__ B,
            const float* __restrict__ bias, OT* __restrict__ C,
            int M, int N, int K, int ldc) {
    extern __shared__ char smem[];
    __half* As = (__half*)smem;
    __half* Bs = (__half*)(smem + 36864);
    float*  Es = (float*)smem;
    int tid = threadIdx.x;
    int warp = tid >> 5;
    int lane = tid & 31;
    int wr = warp & 1;
    int wc = warp >> 1;
    int m0 = blockIdx.y * 128;
    int n0 = blockIdx.x * 128;
    AccFrag acc[4][2];
    auto loadTile = [&](int kt, int buf) {
        int k0 = kt << 6;
        #pragma unroll
        for (int i = 0; i < 4; i++) {
            int c = tid + i * 256;
            int row = c >> 3;
            int off = (c & 7) * 8;
            int m = m0 + row;
            bool ok = (m < M);
            cp16p(s2u(&As[(buf * 128 + row) * LDK + off]), &A[(long)(ok ? m : 0) * K + k0 + off], ok);
            cp16(s2u(&Bs[(buf * 128 + row) * LDK + off]), &B[(long)(n0 + row) * K + k0 + off]);
        }
    };
    gemm_core(smem, K >> 6, loadTile, acc, wr, wc);
    __syncthreads();
    #pragma unroll
    for (int i = 0; i < 4; i++)
        #pragma unroll
        for (int j = 0; j < 2; j++) {
            wmma::store_matrix_sync(&Es[warp * 384], acc[i][j], 24, wmma::mem_row_major);
            __syncwarp();
            #pragma unroll
            for (int e = 0; e < 8; e++) {
                int idx = lane + e * 32;
                int r = idx >> 4;
                int c = idx & 15;
                int m = m0 + wr * 64 + i * 16 + r;
                int n = n0 + wc * 32 + j * 16 + c;
                if (m < M) st_out(&C[(long)m * ldc + n], Es[warp * 384 + r * 24 + c] + bias[n]);
            }
            __syncwarp();
        }
}

// =====================================================================
// gemm16_64: 64x128 core (kv)
// =====================================================================
template<typename OT>
__global__ __launch_bounds__(256)
void gemm16_64(const __half* __restrict__ A, const __half* __restrict__ B,
               const float* __restrict__ bias, OT* __restrict__ C,
               int M, int N, int K, int ldc) {
    extern __shared__ char smem[];
    __half* As = (__half*)smem;
    __half* Bs = (__half*)(smem + 18432);
    float*  Es = (float*)smem;
    int tid = threadIdx.x;
    int warp = tid >> 5;
    int lane = tid & 31;
    int wm = warp >> 2;
    int wn = warp & 3;
    int m0 = blockIdx.y * 64;
    int n0 = blockIdx.x * 128;
    AccFrag acc[2][2];
    auto loadTile = [&](int kt, int buf) {
        int k0 = kt << 6;
        #pragma unroll
        for (int i = 0; i < 2; i++) {
            int c = tid + i * 256;
            int row = c >> 3;
            int off = (c & 7) * 8;
            int m = m0 + row;
            bool ok = (m < M);
            cp16p(s2u(&As[(buf * 64 + row) * LDK + off]), &A[(long)(ok ? m : 0) * K + k0 + off], ok);
        }
        #pragma unroll
        for (int i = 0; i < 4; i++) {
            int c = tid + i * 256;
            int row = c >> 3;
            int off = (c & 7) * 8;
            cp16(s2u(&Bs[(buf * 128 + row) * LDK + off]), &B[(long)(n0 + row) * K + k0 + off]);
        }
    };
    gemm_core64(smem, K >> 6, loadTile, acc, wm, wn);
    __syncthreads();
    #pragma unroll
    for (int i = 0; i < 2; i++)
        #pragma unroll
        for (int j = 0; j < 2; j++) {
            wmma::store_matrix_sync(&Es[warp * 384], acc[i][j], 24, wmma::mem_row_major);
            __syncwarp();
            #pragma unroll
            for (int e = 0; e < 8; e++) {
                int idx = lane + e * 32;
                int r = idx >> 4;
                int c = idx & 15;
                int m = m0 + wm * 32 + i * 16 + r;
                int n = n0 + wn * 32 + j * 16 + c;
                if (m < M) st_out(&C[(long)m * ldc + n], Es[warp * 384 + r * 24 + c] + bias[n]);
            }
            __syncwarp();
        }
}

// =====================================================================
// conv3x3 implicit GEMM (NHWC), 64x128 tiles; M=6272,N=512,K=4608
// =====================================================================
__global__ __launch_bounds__(256)
void conv3_g(const __half* __restrict__ dwt, const __half* __restrict__ w,
             const float* __restrict__ cb, const float* __restrict__ cg,
             const float* __restrict__ cbeta, __half* __restrict__ out) {
    extern __shared__ char smem[];
    float* Es = (float*)smem;
    int tid = threadIdx.x;
    int warp = tid >> 5;
    int lane = tid & 31;
    int wm = warp >> 2;
    int wn = warp & 3;
    int m0 = blockIdx.y * 64;
    int n0 = blockIdx.x * 128;
    __half* As = (__half*)smem;
    __half* Bs = (__half*)(smem + 18432);
    int pre_b[2], pre_y[2], pre_x[2];
    #pragma unroll
    for (int i = 0; i < 2; i++) {
        int c = tid + i * 256;
        int row = c >> 3;
        int m = m0 + row;
        int b = m / P2;
        int p = m - b * P2;
        pre_b[i] = b;
        pre_y[i] = p / 28;
        pre_x[i] = p - (p / 28) * 28;
    }
    AccFrag acc[2][2];
    auto loadTile = [&](int kt, int buf) {
        int k0 = kt << 6;
        #pragma unroll
        for (int i = 0; i < 2; i++) {
            int c = tid + i * 256;
            int row = c >> 3;
            int off = (c & 7) * 8;
            int k = k0 + off;
            int kyx = k >> 9;
            int ic = k & 511;
            int ky = kyx / 3;
            int kx = kyx - ky * 3;
            int iy = pre_y[i] + ky - 1;
            int ix = pre_x[i] + kx - 1;
            bool ok = (iy >= 0 && iy < 28 && ix >= 0 && ix < 28);
            int iyc = ok ? iy : 0;
            int ixc = ok ? ix : 0;
            cp16p(s2u(&As[(buf * 64 + row) * LDK + off]),
                  &dwt[((long)(pre_b[i] * P2 + iyc * 28 + ixc) << 9) + ic], ok);
        }
        #pragma unroll
        for (int i = 0; i < 4; i++) {
            int c = tid + i * 256;
            int row = c >> 3;
            int off = (c & 7) * 8;
            cp16(s2u(&Bs[(buf * 128 + row) * LDK + off]), &w[(long)(n0 + row) * 4608 + k0 + off]);
        }
    };
    gemm_core64(smem, 72, loadTile, acc, wm, wn);
    __syncthreads();
    const float invs = rsqrtf(1.f + 1e-5f);
    #pragma unroll
    for (int i = 0; i < 2; i++)
        #pragma unroll
        for (int j = 0; j < 2; j++) {
            wmma::store_matrix_sync(&Es[warp * 384], acc[i][j], 24, wmma::mem_row_major);
            __syncwarp();
            #pragma unroll
            for (int e = 0; e < 8; e++) {
                int idx = lane + e * 32;
                int r = idx >> 4;
                int c = idx & 15;
                int m = m0 + wm * 32 + i * 16 + r;
                int n = n0 + wn * 32 + j * 16 + c;
                float v = Es[warp * 384 + r * 24 + c] + cb[n];
                v = v * (cg[n] * invs) + cbeta[n];
                out[((long)m << 9) + n] = __float2half(fmaxf(v, 0.f));
            }
            __syncwarp();
        }
}

// =====================================================================
// kve 2x2 s2 conv implicit GEMM, 64x128 tiles; M=1568,N=512,K=2048
// =====================================================================
__global__ __launch_bounds__(256)
void kve_g(const __half* __restrict__ c3, const __half* __restrict__ w,
           const float* __restrict__ bias, float* __restrict__ out) {
    extern __shared__ char smem[];
    float* Es = (float*)smem;
    int tid = threadIdx.x;
    int warp = tid >> 5;
    int lane = tid & 31;
    int wm = warp >> 2;
    int wn = warp & 3;
    int m0 = blockIdx.y * 64;
    int n0 = blockIdx.x * 128;
    __half* As = (__half*)smem;
    __half* Bs = (__half*)(smem + 18432);
    int pre_s[2];
    bool pre_v[2];
    #pragma unroll
    for (int i = 0; i < 2; i++) {
        int c = tid + i * 256;
        int row = c >> 3;
        int m = m0 + row;
        pre_v[i] = (m < BB * MKV);
        int mm = pre_v[i] ? m : 0;
        int b = mm / MKV;
        int p = mm - b * MKV;
        int oy = p / 14;
        int ox = p - (p / 14) * 14;
        pre_s[i] = b * P2 + 2 * oy * 28 + 2 * ox;
    }
    AccFrag acc[2][2];
    auto loadTile = [&](int kt, int buf) {
        int k0 = kt << 6;
        #pragma unroll
        for (int i = 0; i < 2; i++) {
            int c = tid + i * 256;
            int row = c >> 3;
            int off = (c & 7) * 8;
            int k = k0 + off;
            int kyx = k >> 9;
            int ic = k & 511;
            int ky = kyx >> 1;
            int kx = kyx & 1;
            cp16p(s2u(&As[(buf * 64 + row) * LDK + off]),
                  &c3[((long)(pre_s[i] + ky * 28 + kx) << 9) + ic], pre_v[i]);
        }
        #pragma unroll
        for (int i = 0; i < 4; i++) {
            int c = tid + i * 256;
            int row = c >> 3;
            int off = (c & 7) * 8;
            cp16(s2u(&Bs[(buf * 128 + row) * LDK + off]), &w[(long)(n0 + row) * 2048 + k0 + off]);
        }
    };
    gemm_core64(smem, 32, loadTile, acc, wm, wn);
    __syncthreads();
    #pragma unroll
    for (int i = 0; i < 2; i++)
        #pragma unroll
        for (int j = 0; j < 2; j++) {
            wmma::store_matrix_sync(&Es[warp * 384], acc[i][j], 24, wmma::mem_row_major);
            __syncwarp();
            #pragma unroll
            for (int e = 0; e < 8; e++) {
                int idx = lane + e * 32;
                int r = idx >> 4;
                int c = idx & 15;
                int m = m0 + wm * 32 + i * 16 + r;
                int n = n0 + wn * 32 + j * 16 + c;
                if (m < BB * MKV) out[(long)m * CC + n] = Es[warp * 384 + r * 24 + c] + bias[n];
            }
            __syncwarp();
        }
}

// ---------------- BN+ReLU+fp16+DWT ----------------
__global__ void dwt_k(const float* __restrict__ rtmp, const float* __restrict__ g,
                      const float* __restrict__ beta, __half* __restrict__ dwt) {
    int idx = blockIdx.x * blockDim.x + threadIdx.x;
    if (idx >= BB * C4 * P2) return;
    int c = idx & 127;
    int p = (idx >> 7) % P2;
    int b = idx / (C4 * P2);
    int y2 = p / 28;
    int x2 = p % 28;
    float s = g[c] * rsqrtf(1.f + 1e-5f);
    float bt = beta[c];
    const __half hhalf = __float2half(0.5f);
    __half xh[2][2];
    #pragma unroll
    for (int dy = 0; dy < 2; dy++)
        #pragma unroll
        for (int dx = 0; dx < 2; dx++) {
            int n = (2 * y2 + dy) * 56 + (2 * x2 + dx);
            float v = rtmp[((long)(b * NN + n)) * C4 + c];
            v = fmaxf(v * s + bt, 0.f);
            xh[dy][dx] = __hmul(__float2half(v), hhalf);
        }
    __half x1 = xh[0][0], x2h = xh[1][0], x3 = xh[0][1], x4 = xh[1][1];
    __half ll = __hadd(__hadd(__hadd(x1, x2h), x3), x4);
    __half hl = __hadd(__hadd(__hsub(__hneg(x1), x2h), x3), x4);
    __half lh = __hadd(__hsub(__hadd(__hneg(x1), x2h), x3), x4);
    __half hh = __hadd(__hsub(__hsub(x1, x2h), x3), x4);
    long base = ((long)(b * P2 + p) << 9) + c;
    dwt[base]       = ll;
    dwt[base + 128] = hl;
    dwt[base + 256] = lh;
    dwt[base + 384] = hh;
}

// ---------------- IDWT -> cath[:, 512:] ----------------
__global__ void idwt_k(const __half* __restrict__ c3, __half* __restrict__ cat) {
    int idx = blockIdx.x * blockDim.x + threadIdx.x;
    if (idx >= BB * C4 * P2) return;
    int c = idx & 127;
    int p = (idx >> 7) % P2;
    int b = idx / (C4 * P2);
    int y2 = p / 28;
    int x2 = p % 28;
    long base = ((long)(b * P2 + p) << 9) + c;
    __half ll = c3[base], hl = c3[base + 128], lh = c3[base + 256], hh = c3[base + 384];
    const __half hhalf = __float2half(0.5f);
    __half p1 = __hmul(__hadd(__hsub(__hsub(ll, hl), lh), hh), hhalf);
    __half p2 = __hmul(__hsub(__hadd(__hsub(ll, hl), lh), hh), hhalf);
    __half p3 = __hmul(__hsub(__hsub(__hadd(ll, hl), lh), hh), hhalf);
    __half p4 = __hmul(__hadd(__hadd(__hadd(ll, hl), lh), hh), hhalf);
    int n00 = (2 * y2) * 56 + 2 * x2;
    long cb = ((long)(b * NN)) * 640 + 512 + c;
    cat[cb + (long)n00 * 640]        = p1;
    cat[cb + (long)(n00 + 1) * 640]  = p3;
    cat[cb + (long)(n00 + 56) * 640] = p2;
    cat[cb + (long)(n00 + 57) * 640] = p4;
}

// ---------------- LayerNorm ----------------
__global__ void layernorm_k(const float* __restrict__ buf, const float* __restrict__ g,
                            const float* __restrict__ bta, __half* __restrict__ outh) {
    int row = blockIdx.x;
    const float* p = buf + (long)row * CC;
    __shared__ float red[16];
    int tid = threadIdx.x;
    float v = p[tid];
    float s = v;
    #pragma unroll
    for (int o = 16; o > 0; o >>= 1) s += __shfl_xor_sync(~0u, s, o);
    if ((tid & 31) == 0) red[tid >> 5] = s;
    __syncthreads();
    if (tid < 16) {
        float t = red[tid];
        #pragma unroll
        for (int o = 8; o > 0; o >>= 1) t += __shfl_xor_sync(0xffffu, t, o);
        if (tid == 0) red[0] = t;
    }
    __syncthreads();
    float mu = red[0] * (1.f / 512.f);
    __syncthreads();
    float d = v - mu;
    float s2 = d * d;
    #pragma unroll
    for (int o = 16; o > 0; o >>= 1) s2 += __shfl_xor_sync(~0u, s2, o);
    if ((tid & 31) == 0) red[tid >> 5] = s2;
    __syncthreads();
    if (tid < 16) {
        float t = red[tid];
        #pragma unroll
        for (int o = 8; o > 0; o >>= 1) t += __shfl_xor_sync(0xffffu, t, o);
        if (tid == 0) red[0] = t;
    }
    __syncthreads();
    float var = red[0] * (1.f / 512.f);
    outh[(long)row * CC + tid] = __float2half(d * (1.f / sqrtf(var + 1e-5f)) * g[tid] + bta[tid]);
}

// =====================================================================
// WMMA attention, 192 q rows per block (3 x 64-row subtiles share K/V)
// smem: qs 192x80h | ks 224x80h | vs 224x80h | Ps 64x240h | Ss 64x232f
// =====================================================================
#define ATTN_SMEM (192*80*2 + 224*80*2*2 + 64*240*2 + 64*232*4)
__global__ __launch_bounds__(256)
void attn_w(const __half* __restrict__ qh, const __half* __restrict__ kvh,
            __half* __restrict__ cat) {
    extern __shared__ char smem[];
    __half* qs  = (__half*)smem;                             // 192 x 80
    __half* ks  = (__half*)(smem + 30720);                   // 224 x 80
    __half* vs  = (__half*)(smem + 30720 + 35840);           // 224 x 80
    __half* Ps  = (__half*)(smem + 30720 + 71680);           // 64 x 240
    float*  Ss  = (float*)(smem + 30720 + 71680 + 30720);    // 64 x 232
    int b = blockIdx.x >> 3;
    int h = blockIdx.x & 7;
    int n0 = blockIdx.y * 192;
    int rem = NN - n0;
    int nsub = (rem >= 192) ? 3 : ((rem + 63) >> 6);
    int tid = threadIdx.x;
    int warp = tid >> 5;
    int lane = tid & 31;

    #pragma unroll
    for (int i = 0; i < 6; i++) {
        int c = tid + i * 256;
        int row = c >> 3;
        int off = (c & 7) * 8;
        bool ok = (n0 + row < NN);
        int rowc = ok ? row : 0;
        cp16p(s2u(&qs[row * 80 + off]), &qh[((long)(b * NN + n0 + rowc) << 9) + h * 64 + off], ok);
    }
    #pragma unroll
    for (int i = 0; i < 7; i++) {
        int c = tid + i * 256;
        int row = c >> 3;
        int off = (c & 7) * 8;
        bool ok = row < MKV;
        int rc = ok ? row : 0;
        const __half* base = &kvh[((long)(b * MKV + rc) << 10) + h * 64 + off];
        cp16p(s2u(&ks[row * 80 + off]), base, ok);
        cp16p(s2u(&vs[row * 80 + off]), base + 512, ok);
    }
    cpcommit(); cpwait0();
    __syncthreads();

    for (int qt = 0; qt < nsub; qt++) {
        __half* qsub = qs + qt * 64 * 80;
        {
            int mr = warp >> 1;
            int nh = warp & 1;
            wmma::fragment<wmma::accumulator, 16, 16, 16, float> sacc[7];
            #pragma unroll
            for (int j = 0; j < 7; j++) wmma::fill_fragment(sacc[j], 0.f);
            #pragma unroll
            for (int kk = 0; kk < 64; kk += 16) {
                wmma::fragment<wmma::matrix_a, 16, 16, 16, __half, wmma::row_major> af;
                wmma::load_matrix_sync(af, &qsub[(mr * 16) * 80 + kk], 80);
                #pragma unroll
                for (int j = 0; j < 7; j++) {
                    wmma::fragment<wmma::matrix_b, 16, 16, 16, __half, wmma::col_major> bf;
                    wmma::load_matrix_sync(bf, &ks[((nh * 7 + j) * 16) * 80 + kk], 80);
                    wmma::mma_sync(sacc[j], af, bf, sacc[j]);
                }
            }
            #pragma unroll
            for (int j = 0; j < 7; j++)
                wmma::store_matrix_sync(&Ss[(mr * 16) * 232 + (nh * 7 + j) * 16], sacc[j], 232,
                                        wmma::mem_row_major);
        }
        __syncthreads();

        for (int it = 0; it < 8; it++) {
            int r = it * 8 + warp;
            float sv[7];
            float mx = -1e30f;
            #pragma unroll
            for (int j = 0; j < 7; j++) {
                int col = lane + 32 * j;
                sv[j] = Ss[r * 232 + col] * 0.125f;
                if (col < MKV) mx = fmaxf(mx, sv[j]);
            }
            #pragma unroll
            for (int o = 16; o > 0; o >>= 1) mx = fmaxf(mx, __shfl_xor_sync(~0u, mx, o));
            float sum = 0.f;
            float pr[7];
            #pragma unroll
            for (int j = 0; j < 7; j++) {
                int col = lane + 32 * j;
                pr[j] = (col < MKV) ? __expf(sv[j] - mx) : 0.f;
                sum += pr[j];
            }
            #pragma unroll
            for (int o = 16; o > 0; o >>= 1) sum += __shfl_xor_sync(~0u, sum, o);
            float inv = 1.f / sum;
            #pragma unroll
            for (int j = 0; j < 7; j++) {
                int col = lane + 32 * j;
                Ps[r * 240 + col] = __float2half(pr[j] * inv);
            }
        }
        __syncthreads();

        {
            int mr = warp >> 1;
            int nc = warp & 1;
            wmma::fragment<wmma::accumulator, 16, 16, 16, float> oacc[2];
            #pragma unroll
            for (int j = 0; j < 2; j++) wmma::fill_fragment(oacc[j], 0.f);
            #pragma unroll
            for (int k = 0; k < 14; k++) {
                wmma::fragment<wmma::matrix_a, 16, 16, 16, __half, wmma::row_major> af;
                wmma::load_matrix_sync(af, &Ps[(mr * 16) * 240 + k * 16], 240);
                #pragma unroll
                for (int j = 0; j < 2; j++) {
                    wmma::fragment<wmma::matrix_b, 16, 16, 16, __half, wmma::row_major> bf;
                    wmma::load_matrix_sync(bf, &vs[(k * 16) * 80 + (nc * 2 + j) * 16], 80);
                    wmma::mma_sync(oacc[j], af, bf, oacc[j]);
                }
            }
            float* Es = Ss + warp * 384;
            #pragma unroll
            for (int j = 0; j < 2; j++) {
                wmma::store_matrix_sync(Es, oacc[j], 24, wmma::mem_row_major);
                __syncwarp();
                #pragma unroll
                for (int e = 0; e < 8; e++) {
                    int idx = lane + e * 32;
                    int r = idx >> 4;
                    int c = idx & 15;
                    int m = n0 + qt * 64 + mr * 16 + r;
                    int n = (nc * 2 + j) * 16 + c;
                    if (m < NN)
                        cat[((long)(b * NN + m)) * 640 + h * 64 + n] = __float2half(Es[r * 24 + c]);
                }
                __syncwarp();
            }
        }
        __syncthreads();
    }
}

// ---------------- launch ----------------
extern "C" void kernel_launch(void* const* d_in, const int* in_sizes, int n_in,
                              void* d_out, int out_size) {
    const float* x           = (const float*)d_in[0];
    const float* reduce_w    = (const float*)d_in[3];
    const float* reduce_b    = (const float*)d_in[4];
    const float* reduce_g    = (const float*)d_in[5];
    const float* reduce_beta = (const float*)d_in[6];
    const float* filter_w    = (const float*)d_in[7];
    const float* filter_b    = (const float*)d_in[8];
    const float* filter_g    = (const float*)d_in[9];
    const float* filter_beta = (const float*)d_in[10];
    const float* q_w         = (const float*)d_in[11];
    const float* q_b         = (const float*)d_in[12];
    const float* ln_g        = (const float*)d_in[13];
    const float* ln_b        = (const float*)d_in[14];
    const float* kv_w        = (const float*)d_in[15];
    const float* kv_b        = (const float*)d_in[16];
    const float* kve_w       = (const float*)d_in[17];
    const float* kve_b       = (const float*)d_in[18];
    const float* proj_w      = (const float*)d_in[19];
    const float* proj_b      = (const float*)d_in[20];
    float* out = (float*)d_out;

    __half *xh, *qh, *dwtbuf, *c3, *kvinh, *kvh, *cath;
    __half *wcomb, *fwh, *kvewh, *kvwh, *pwh;
    float *rtmp, *kvin;
    cudaGetSymbolAddress((void**)&xh,    g_xh);
    cudaGetSymbolAddress((void**)&qh,    g_qh);
    cudaGetSymbolAddress((void**)&rtmp,  g_rtmp);
    cudaGetSymbolAddress((void**)&dwtbuf,g_dwt);
    cudaGetSymbolAddress((void**)&c3,    g_c3);
    cudaGetSymbolAddress((void**)&kvin,  g_kvin);
    cudaGetSymbolAddress((void**)&kvinh, g_kvinh);
    cudaGetSymbolAddress((void**)&kvh,   g_kvh);
    cudaGetSymbolAddress((void**)&cath,  g_cath);
    cudaGetSymbolAddress((void**)&wcomb, g_wcomb);
    cudaGetSymbolAddress((void**)&fwh,   g_fwh);
    cudaGetSymbolAddress((void**)&kvewh, g_kvewh);
    cudaGetSymbolAddress((void**)&kvwh,  g_kvwh);
    cudaGetSymbolAddress((void**)&pwh,   g_pwh);

    static int inited = 0;
    static cudaStream_t s1;
    static cudaEvent_t evFork, evQW, evW3, evW2, evKVW, evPW, evConv, evI;
    if (!inited) {
        cudaFuncSetAttribute(qr_gemm, cudaFuncAttributeMaxDynamicSharedMemorySize, GEMM_SMEM);
        cudaFuncSetAttribute(gemm16<float>, cudaFuncAttributeMaxDynamicSharedMemorySize, GEMM_SMEM);
        cudaFuncSetAttribute(gemm16_64<__half>, cudaFuncAttributeMaxDynamicSharedMemorySize, GEMM64_SMEM);
        cudaFuncSetAttribute(conv3_g, cudaFuncAttributeMaxDynamicSharedMemorySize, GEMM64_SMEM);
        cudaFuncSetAttribute(kve_g, cudaFuncAttributeMaxDynamicSharedMemorySize, GEMM64_SMEM);
        cudaFuncSetAttribute(attn_w, cudaFuncAttributeMaxDynamicSharedMemorySize, ATTN_SMEM);
        cudaStreamCreateWithFlags(&s1, cudaStreamNonBlocking);
        cudaEventCreateWithFlags(&evFork, cudaEventDisableTiming);
        cudaEventCreateWithFlags(&evQW,   cudaEventDisableTiming);
        cudaEventCreateWithFlags(&evW3,   cudaEventDisableTiming);
        cudaEventCreateWithFlags(&evW2,   cudaEventDisableTiming);
        cudaEventCreateWithFlags(&evKVW,  cudaEventDisableTiming);
        cudaEventCreateWithFlags(&evPW,   cudaEventDisableTiming);
        cudaEventCreateWithFlags(&evConv, cudaEventDisableTiming);
        cudaEventCreateWithFlags(&evI,    cudaEventDisableTiming);
        inited = 1;
    }

    cudaStream_t s0 = 0;

    cudaEventRecord(evFork, s0);
    cudaStreamWaitEvent(s1, evFork, 0);

    // ---- s1: weight prep ----
    f2h8<<<(CC * CC / 8 + 255) / 256, 256, 0, s1>>>(q_w, wcomb, CC * CC);
    f2h8<<<(C4 * CC / 8 + 255) / 256, 256, 0, s1>>>(reduce_w, wcomb + CC * CC, C4 * CC);
    cudaEventRecord(evQW, s1);
    reorder_w3<<<(512 * 4608 + 255) / 256, 256, 0, s1>>>(filter_w, fwh);
    cudaEventRecord(evW3, s1);
    reorder_w2<<<(512 * 2048 + 255) / 256, 256, 0, s1>>>(kve_w, kvewh);
    cudaEventRecord(evW2, s1);
    f2h8<<<(2 * CC * CC / 8 + 255) / 256, 256, 0, s1>>>(kv_w, kvwh, 2 * CC * CC);
    cudaEventRecord(evKVW, s1);
    f2h8<<<(CC * (CC + C4) / 8 + 255) / 256, 256, 0, s1>>>(proj_w, pwh, CC * (CC + C4));
    cudaEventRecord(evPW, s1);

    // ---- s0 critical chain ----
    f2h8<<<(MTOK * CC / 8 + 255) / 256, 256, 0, s0>>>(x, xh, MTOK * CC);
    cudaStreamWaitEvent(s0, evQW, 0);
    qr_gemm<<<dim3(5, 196), 256, GEMM_SMEM, s0>>>(xh, wcomb, q_b, reduce_b, qh, rtmp);
    dwt_k<<<(BB * C4 * P2 + 255) / 256, 256, 0, s0>>>(rtmp, reduce_g, reduce_beta, dwtbuf);
    cudaStreamWaitEvent(s0, evW3, 0);
    conv3_g<<<dim3(4, 98), 256, GEMM64_SMEM, s0>>>(dwtbuf, fwh, filter_b, filter_g, filter_beta, c3);
    cudaEventRecord(evConv, s0);

    // ---- s1: idwt ----
    cudaStreamWaitEvent(s1, evConv, 0);
    idwt_k<<<(BB * C4 * P2 + 255) / 256, 256, 0, s1>>>(c3, cath);
    cudaEventRecord(evI, s1);

    // ---- s0: kve -> LN -> kv -> attn ----
    cudaStreamWaitEvent(s0, evW2, 0);
    kve_g<<<dim3(4, 25), 256, GEMM64_SMEM, s0>>>(c3, kvewh, kve_b, kvin);
    layernorm_k<<<BB * MKV, 512, 0, s0>>>(kvin, ln_g, ln_b, kvinh);
    cudaStreamWaitEvent(s0, evKVW, 0);
    gemm16_64<__half><<<dim3(8, 25), 256, GEMM64_SMEM, s0>>>(kvinh, kvwh, kv_b, kvh, BB * MKV, 2 * CC, CC, 2 * CC);
    attn_w<<<dim3(BB * NHEADS, 17), 256, ATTN_SMEM, s0>>>(qh, kvh, cath);

    // ---- s0: proj ----
    cudaStreamWaitEvent(s0, evI, 0);
    cudaStreamWaitEvent(s0, evPW, 0);
    gemm16<float><<<dim3(4, 196), 256, GEMM_SMEM, s0>>>(cath, pwh, proj_b, out, MTOK, CC, CC + C4, CC);
}